// round 2
// baseline (speedup 1.0000x reference)
#include <cuda_runtime.h>
#include <math.h>

// Problem constants
#define SS   4096
#define BB   16
#define CC   512
#define TMAX 512

// ---------------- device scratch (static allocation; no cudaMalloc) ----------------
__device__ float g_alpha[BB * SS];          // scaled alpha
__device__ float g_csum [BB * SS];          // fp32 assoc-scan cumsum
__device__ int   g_f    [BB * SS];          // floor(csum + 1e-4)
__device__ float g_feats[BB * TMAX * 512];  // feats, K padded to 512 (col 511 = 0)
__device__ float g_Wp   [512 * 512];        // W padded to 512x512 (col 511 = 0)

// level offsets for the 4096-element associative-scan buffers in smem
__constant__ int c_off[13] = {0,4096,6144,7168,7680,7936,8064,8128,8160,8176,8184,8188,8190};

// ---------------- packed f32x2 helpers (FFMA2 path: 2x fp32 throughput) -------------
__device__ __forceinline__ void fma2(unsigned long long& d,
                                     unsigned long long a,
                                     unsigned long long b) {
    asm("fma.rn.f32x2 %0, %1, %2, %0;" : "+l"(d) : "l"(a), "l"(b));
}
__device__ __forceinline__ unsigned long long pk2(float x, float y) {
    unsigned long long r;
    asm("mov.b64 %0, {%1, %2};" : "=l"(r) : "f"(x), "f"(y));
    return r;
}
__device__ __forceinline__ float2 upk2(unsigned long long p) {
    float2 f;
    asm("mov.b64 {%0, %1}, %2;" : "=f"(f.x), "=f"(f.y) : "l"(p));
    return f;
}

// ---------------- Phase 1: alpha, alpha_sum, exact JAX-tree cumsum, fire indices ----
__device__ __forceinline__ void downsweep(float* sb, int tid) {
    for (int l = 1; l <= 12; l++) {
        int sz = SS >> l;
        int o  = c_off[l], oi = c_off[l-1];
        for (int i = tid; i < sz; i += 512)
            sb[o + i] = sb[oi + 2*i] + sb[oi + 2*i + 1];
        __syncthreads();
    }
}

__device__ __forceinline__ void upsweep(float* sb, int tid) {
    for (int l = 11; l >= 0; l--) {
        int sz = SS >> l;
        int o  = c_off[l], ou = c_off[l+1];
        for (int i = tid; i < sz; i += 512) {
            float v;
            if (i & 1)          v = sb[ou + (i >> 1)];
            else if (i == 0)    v = sb[o];
            else                v = sb[ou + (i >> 1) - 1] + sb[o + i];
            sb[o + i] = v;
        }
        __syncthreads();
    }
}

__global__ __launch_bounds__(512)
void phase1_kernel(const float* __restrict__ x,
                   const unsigned char* __restrict__ mask,
                   const int* __restrict__ tl,
                   float* __restrict__ alpha_sum_out) {
    __shared__ float sb[8192];
    int b   = blockIdx.x;
    int tid = threadIdx.x;

    for (int s = tid; s < SS; s += 512) {
        float a = mask[b * SS + s] ? -10000.0f : x[(size_t)s * (BB*CC) + b * CC + (CC - 1)];
        double sg = 1.0 / (1.0 + exp(-(double)a));
        sb[s] = (float)sg;
    }
    __syncthreads();

    downsweep(sb, tid);
    float asum = sb[c_off[12]];
    if (tid == 0) alpha_sum_out[b] = asum;
    float tlf = (float)tl[b];
    __syncthreads();

    for (int s = tid; s < SS; s += 512) {
        float sc = (sb[s] * tlf) / asum;
        sb[s] = sc;
        g_alpha[b * SS + s] = sc;
    }
    __syncthreads();

    downsweep(sb, tid);
    upsweep(sb, tid);

    for (int s = tid; s < SS; s += 512) {
        float c = sb[s];
        g_csum[b * SS + s] = c;
        g_f  [b * SS + s] = (int)floorf(c + 1e-4f);
    }
}

// ---------------- Phase 1b: pad W (512,511) -> g_Wp (512,512), col 511 = 0 ----------
__global__ void prep_w_kernel(const float* __restrict__ W) {
    int i = blockIdx.x * 256 + threadIdx.x;
    if (i < 512 * 512) {
        int k = i & 511;
        int n = i >> 9;
        g_Wp[i] = (k < 511) ? W[n * 511 + k] : 0.0f;
    }
}

// ---------------- Phase 2: sparse gather, TT=8 t-values per block --------------------
#define TT 8

__global__ __launch_bounds__(128)
void gather_kernel(const float* __restrict__ x) {
    int blk = blockIdx.x;              // b * (512/TT) + tg
    int b   = blk >> 6;                // 512/TT = 64
    int t0  = (blk & 63) * TT;
    const int*   f  = g_f     + b * SS;
    const float* al = g_alpha + b * SS;
    const float* cs = g_csum  + b * SS;

    // union window for t in [t0, t0+TT-1]:
    // lo = first s with f[s] >= t0-1 ; hi = min(first s with f[s] > t0+TT-1, S-1)
    int lo, hi;
    {
        int l = 0, r = SS;
        while (l < r) { int m = (l + r) >> 1; if (f[m] >= t0 - 1) r = m; else l = m + 1; }
        lo = l;
        l = 0; r = SS;
        while (l < r) { int m = (l + r) >> 1; if (f[m] > t0 + TT - 1) r = m; else l = m + 1; }
        hi = (l < SS - 1) ? l : SS - 1;
    }

    __shared__ float wbuf[TT][128];
    int tid = threadIdx.x;
    int c0  = tid * 4;
    float4 acc[TT];
    #pragma unroll
    for (int tt = 0; tt < TT; tt++) acc[tt] = make_float4(0.f, 0.f, 0.f, 0.f);

    for (int base = lo; base <= hi; base += 128) {
        int s = base + tid;
        if (s <= hi) {
            int   d1   = f[s];
            int   d0   = (s == 0) ? 0 : f[s - 1];
            int   fire = d1 - d0;
            float a    = al[s];
            float c    = cs[s];
            float ex   = (fire > 1) ? (float)(fire - 1) : 0.f;
            float rw   = (fire > 0) ? (c - (float)d1) : a;
            float lw   = (a - rw) - ex;
            int   ei   = d0 + 1; if (ei > TMAX - 1) ei = TMAX - 1;
            float exc  = fminf(ex, 1.0f);
            #pragma unroll
            for (int tt = 0; tt < TT; tt++) {
                int t = t0 + tt;
                float w = 0.f;
                if (d1 == t) w += rw;
                if (d0 == t) w += lw;
                if (ei == t) w += exc;
                if (t >= d0 + 2 && t < d1) w = 1.0f;   // fill overwrite
                wbuf[tt][tid] = w;
            }
        } else {
            #pragma unroll
            for (int tt = 0; tt < TT; tt++) wbuf[tt][tid] = 0.f;
        }
        __syncthreads();

        int n = hi - base + 1; if (n > 128) n = 128;
        const float* xp = x + (size_t)base * (BB*CC) + b * CC + c0;
        #pragma unroll 2
        for (int j = 0; j < n; j++) {
            float4 v = *(const float4*)(xp + (size_t)j * (BB*CC));
            #pragma unroll
            for (int tt = 0; tt < TT; tt++) {
                float wj = wbuf[tt][j];
                acc[tt].x += wj * v.x; acc[tt].y += wj * v.y;
                acc[tt].z += wj * v.z; acc[tt].w += wj * v.w;
            }
        }
        __syncthreads();
    }

    #pragma unroll
    for (int tt = 0; tt < TT; tt++) {
        float4 a = acc[tt];
        if (c0 == 508) a.w = 0.f;   // channel 511 excluded (pad = 0)
        *(float4*)(g_feats + ((size_t)(b * 512 + t0 + tt)) * 512 + c0) = a;
    }
}

// ---------------- Phase 3: fp32 GEMM with FFMA2 (packed f32x2) -----------------------
// M=8192, N=512, K=512. BM=BN=128, BK=16, 256 threads, 8x8 per thread (4 f32x2 pairs).
#define BM 128
#define BN 128
#define BK 16
#define PAD 4

__global__ __launch_bounds__(256, 2)
void gemm_kernel(const float* __restrict__ bias, float* __restrict__ out) {
    __shared__ float As[BK][BM + PAD];
    __shared__ float Bs[BK][BN + PAD];

    int bm  = blockIdx.x * BM;
    int bn  = blockIdx.y * BN;
    int tid = threadIdx.x;
    int tx  = tid & 15;
    int ty  = tid >> 4;

    // gmem load coordinates (same for both A and B tiles)
    int lrow = tid >> 2;            // 0..63
    int lk   = (tid & 3) * 4;       // 0,4,8,12

    unsigned long long acc[8][4];
    #pragma unroll
    for (int i = 0; i < 8; i++)
        #pragma unroll
        for (int j = 0; j < 4; j++) acc[i][j] = 0ull;

    // prefetch first tile into registers
    float4 pa[2], pb[2];
    #pragma unroll
    for (int r = 0; r < 2; r++) {
        pa[r] = *(const float4*)(g_feats + (size_t)(bm + lrow + 64 * r) * 512 + lk);
        pb[r] = *(const float4*)(g_Wp    + (size_t)(bn + lrow + 64 * r) * 512 + lk);
    }

    for (int k0 = 0; k0 < 512; k0 += BK) {
        // commit prefetched tile to smem
        #pragma unroll
        for (int r = 0; r < 2; r++) {
            int row = lrow + 64 * r;
            As[lk + 0][row] = pa[r].x; As[lk + 1][row] = pa[r].y;
            As[lk + 2][row] = pa[r].z; As[lk + 3][row] = pa[r].w;
            Bs[lk + 0][row] = pb[r].x; Bs[lk + 1][row] = pb[r].y;
            Bs[lk + 2][row] = pb[r].z; Bs[lk + 3][row] = pb[r].w;
        }
        __syncthreads();

        // prefetch next tile while computing
        if (k0 + BK < 512) {
            #pragma unroll
            for (int r = 0; r < 2; r++) {
                pa[r] = *(const float4*)(g_feats + (size_t)(bm + lrow + 64 * r) * 512 + k0 + BK + lk);
                pb[r] = *(const float4*)(g_Wp    + (size_t)(bn + lrow + 64 * r) * 512 + k0 + BK + lk);
            }
        }

        #pragma unroll
        for (int kk = 0; kk < BK; kk++) {
            float4 a0 = *(const float4*)&As[kk][ty * 8];
            float4 a1 = *(const float4*)&As[kk][ty * 8 + 4];
            float4 b0 = *(const float4*)&Bs[kk][tx * 8];
            float4 b1 = *(const float4*)&Bs[kk][tx * 8 + 4];
            unsigned long long bb[4];
            bb[0] = pk2(b0.x, b0.y); bb[1] = pk2(b0.z, b0.w);
            bb[2] = pk2(b1.x, b1.y); bb[3] = pk2(b1.z, b1.w);
            float af[8] = {a0.x, a0.y, a0.z, a0.w, a1.x, a1.y, a1.z, a1.w};
            #pragma unroll
            for (int i = 0; i < 8; i++) {
                unsigned long long aa = pk2(af[i], af[i]);
                fma2(acc[i][0], aa, bb[0]);
                fma2(acc[i][1], aa, bb[1]);
                fma2(acc[i][2], aa, bb[2]);
                fma2(acc[i][3], aa, bb[3]);
            }
        }
        __syncthreads();
    }

    float bv[8];
    #pragma unroll
    for (int j = 0; j < 8; j++) bv[j] = bias[bn + tx * 8 + j];

    // out layout: (T, B, C): idx = t*(B*C) + b*C + n, with m = b*512 + t
    #pragma unroll
    for (int i = 0; i < 8; i++) {
        int m  = bm + ty * 8 + i;
        int b  = m >> 9;
        int t  = m & 511;
        float* op = out + (size_t)t * (BB * CC) + b * CC + bn + tx * 8;
        float2 p0 = upk2(acc[i][0]);
        float2 p1 = upk2(acc[i][1]);
        float2 p2 = upk2(acc[i][2]);
        float2 p3 = upk2(acc[i][3]);
        float4 v0, v1;
        v0.x = p0.x + bv[0]; v0.y = p0.y + bv[1];
        v0.z = p1.x + bv[2]; v0.w = p1.y + bv[3];
        v1.x = p2.x + bv[4]; v1.y = p2.y + bv[5];
        v1.z = p3.x + bv[6]; v1.w = p3.y + bv[7];
        *(float4*)(op + 0) = v0;
        *(float4*)(op + 4) = v1;
    }
}

// ---------------- launch ------------------------------------------------------------
extern "C" void kernel_launch(void* const* d_in, const int* in_sizes, int n_in,
                              void* d_out, int out_size) {
    const float*         x    = (const float*)d_in[0];
    const unsigned char* mask = (const unsigned char*)d_in[1];
    const int*           tl   = (const int*)d_in[2];
    const float*         W    = (const float*)d_in[3];
    const float*         bias = (const float*)d_in[4];
    float*               out  = (float*)d_out;

    float* asum_out = out + (size_t)TMAX * BB * CC;

    phase1_kernel<<<BB, 512>>>(x, mask, tl, asum_out);
    prep_w_kernel<<<(512 * 512 + 255) / 256, 256>>>(W);
    gather_kernel<<<BB * (TMAX / TT), 128>>>(x);
    gemm_kernel<<<dim3(8192 / BM, 512 / BN), 256>>>(bias, out);
}

// round 4
// speedup vs baseline: 1.1289x; 1.1289x over previous
#include <cuda_runtime.h>
#include <cuda_bf16.h>
#include <math.h>
#include <stdint.h>

// Problem constants
#define SS   4096
#define BB   16
#define CC   512
#define TMAX 512

// ---------------- device scratch (static; no cudaMalloc) ----------------------------
__device__ float g_alpha[BB * SS];
__device__ float g_csum [BB * SS];
__device__ int   g_f    [BB * SS];
// A = feats bf16 split, row-major [8192][512]
__device__ __align__(16) __nv_bfloat16 g_Ah[8192 * 512];
__device__ __align__(16) __nv_bfloat16 g_Al[8192 * 512];
// B = W bf16 split, row-major [n=512][k=512] (k 511 padded to 0)
__device__ __align__(16) __nv_bfloat16 g_Bh[512 * 512];
__device__ __align__(16) __nv_bfloat16 g_Bl[512 * 512];

__constant__ int c_off[13] = {0,4096,6144,7168,7680,7936,8064,8128,8160,8176,8184,8188,8190};

// ---------------- Phase 1: alpha, alpha_sum, exact JAX-tree cumsum, fire indices ----
__device__ __forceinline__ void downsweep(float* sb, int tid) {
    for (int l = 1; l <= 12; l++) {
        int sz = SS >> l;
        int o  = c_off[l], oi = c_off[l-1];
        for (int i = tid; i < sz; i += 512)
            sb[o + i] = sb[oi + 2*i] + sb[oi + 2*i + 1];
        __syncthreads();
    }
}
__device__ __forceinline__ void upsweep(float* sb, int tid) {
    for (int l = 11; l >= 0; l--) {
        int sz = SS >> l;
        int o  = c_off[l], ou = c_off[l+1];
        for (int i = tid; i < sz; i += 512) {
            float v;
            if (i & 1)          v = sb[ou + (i >> 1)];
            else if (i == 0)    v = sb[o];
            else                v = sb[ou + (i >> 1) - 1] + sb[o + i];
            sb[o + i] = v;
        }
        __syncthreads();
    }
}

__global__ __launch_bounds__(512)
void phase1_kernel(const float* __restrict__ x,
                   const unsigned char* __restrict__ mask,
                   const int* __restrict__ tl,
                   float* __restrict__ alpha_sum_out) {
    __shared__ float sb[8192];
    int b   = blockIdx.x;
    int tid = threadIdx.x;

    for (int s = tid; s < SS; s += 512) {
        float a = mask[b * SS + s] ? -10000.0f : x[(size_t)s * (BB*CC) + b * CC + (CC - 1)];
        double sg = 1.0 / (1.0 + exp(-(double)a));
        sb[s] = (float)sg;
    }
    __syncthreads();

    downsweep(sb, tid);
    float asum = sb[c_off[12]];
    if (tid == 0) alpha_sum_out[b] = asum;
    float tlf = (float)tl[b];
    __syncthreads();

    for (int s = tid; s < SS; s += 512) {
        float sc = (sb[s] * tlf) / asum;
        sb[s] = sc;
        g_alpha[b * SS + s] = sc;
    }
    __syncthreads();

    downsweep(sb, tid);
    upsweep(sb, tid);

    for (int s = tid; s < SS; s += 512) {
        float c = sb[s];
        g_csum[b * SS + s] = c;
        g_f  [b * SS + s] = (int)floorf(c + 1e-4f);
    }
}

// ---------------- Phase 1b: W -> bf16 hi/lo, row-major [n][k] -----------------------
__global__ void prep_w_kernel(const float* __restrict__ W) {
    int i = blockIdx.x * 256 + threadIdx.x;
    if (i >= 512 * 512) return;
    int n = i >> 9;
    int k = i & 511;
    float v = (k < 511) ? W[n * 511 + k] : 0.0f;
    __nv_bfloat16 hi = __float2bfloat16(v);
    __nv_bfloat16 lo = __float2bfloat16(v - __bfloat162float(hi));
    g_Bh[i] = hi;
    g_Bl[i] = lo;
}

// ---------------- Phase 2: sparse gather, TT=8, mask-skipped loads ------------------
#define TT 8

__global__ __launch_bounds__(128)
void gather_kernel(const float* __restrict__ x) {
    int blk = blockIdx.x;              // b * 64 + tg
    int b   = blk >> 6;
    int t0  = (blk & 63) * TT;
    const int*   f  = g_f     + b * SS;
    const float* al = g_alpha + b * SS;
    const float* cs = g_csum  + b * SS;

    int lo, hi;
    {
        int l = 0, r = SS;
        while (l < r) { int m = (l + r) >> 1; if (f[m] >= t0 - 1) r = m; else l = m + 1; }
        lo = l;
        l = 0; r = SS;
        while (l < r) { int m = (l + r) >> 1; if (f[m] > t0 + TT - 1) r = m; else l = m + 1; }
        hi = (l < SS - 1) ? l : SS - 1;
    }

    __shared__ float    wbuf[TT][128];
    __shared__ unsigned wmask[128];
    int tid = threadIdx.x;
    int c0  = tid * 4;
    float4 acc[TT];
    #pragma unroll
    for (int tt = 0; tt < TT; tt++) acc[tt] = make_float4(0.f, 0.f, 0.f, 0.f);

    for (int base = lo; base <= hi; base += 128) {
        int s = base + tid;
        unsigned msk = 0;
        if (s <= hi) {
            int   d1   = f[s];
            int   d0   = (s == 0) ? 0 : f[s - 1];
            int   fire = d1 - d0;
            float a    = al[s];
            float c    = cs[s];
            float ex   = (fire > 1) ? (float)(fire - 1) : 0.f;
            float rw   = (fire > 0) ? (c - (float)d1) : a;
            float lw   = (a - rw) - ex;
            int   ei   = d0 + 1; if (ei > TMAX - 1) ei = TMAX - 1;
            float exc  = fminf(ex, 1.0f);
            #pragma unroll
            for (int tt = 0; tt < TT; tt++) {
                int t = t0 + tt;
                float w = 0.f;
                if (d1 == t) w += rw;
                if (d0 == t) w += lw;
                if (ei == t) w += exc;
                if (t >= d0 + 2 && t < d1) w = 1.0f;   // fill overwrite
                wbuf[tt][tid] = w;
                if (w != 0.f) msk |= (1u << tt);
            }
        } else {
            #pragma unroll
            for (int tt = 0; tt < TT; tt++) wbuf[tt][tid] = 0.f;
        }
        wmask[tid] = msk;
        __syncthreads();

        int n = hi - base + 1; if (n > 128) n = 128;
        const float* xp = x + (size_t)base * (BB*CC) + b * CC + c0;
        for (int j = 0; j < n; j++) {
            unsigned m = wmask[j];
            if (!m) continue;
            float4 v = *(const float4*)(xp + (size_t)j * (BB*CC));
            #pragma unroll
            for (int tt = 0; tt < TT; tt++) {
                if (m & (1u << tt)) {
                    float wj = wbuf[tt][j];
                    acc[tt].x += wj * v.x; acc[tt].y += wj * v.y;
                    acc[tt].z += wj * v.z; acc[tt].w += wj * v.w;
                }
            }
        }
        __syncthreads();
    }

    // emit bf16 hi/lo rows
    #pragma unroll
    for (int tt = 0; tt < TT; tt++) {
        float4 a = acc[tt];
        if (c0 == 508) a.w = 0.f;   // channel 511 excluded
        __nv_bfloat16 h0 = __float2bfloat16(a.x), h1 = __float2bfloat16(a.y);
        __nv_bfloat16 h2 = __float2bfloat16(a.z), h3 = __float2bfloat16(a.w);
        __nv_bfloat16 l0 = __float2bfloat16(a.x - __bfloat162float(h0));
        __nv_bfloat16 l1 = __float2bfloat16(a.y - __bfloat162float(h1));
        __nv_bfloat16 l2 = __float2bfloat16(a.z - __bfloat162float(h2));
        __nv_bfloat16 l3 = __float2bfloat16(a.w - __bfloat162float(h3));
        uint2 uh, ul;
        uh.x = (unsigned)__bfloat16_as_ushort(h0) | ((unsigned)__bfloat16_as_ushort(h1) << 16);
        uh.y = (unsigned)__bfloat16_as_ushort(h2) | ((unsigned)__bfloat16_as_ushort(h3) << 16);
        ul.x = (unsigned)__bfloat16_as_ushort(l0) | ((unsigned)__bfloat16_as_ushort(l1) << 16);
        ul.y = (unsigned)__bfloat16_as_ushort(l2) | ((unsigned)__bfloat16_as_ushort(l3) << 16);
        size_t o = (size_t)(b * 512 + t0 + tt) * 512 + c0;
        *(uint2*)&g_Ah[o] = uh;
        *(uint2*)&g_Al[o] = ul;
    }
}

// ---------------- Phase 3: bf16 split GEMM on mma.sync (HMMA, base ISA) -------------
// M=8192, N=512, K=512. Block 128x128, BK=32, 8 warps (2x4), warp tile 64x32.
#define GBM 128
#define GBN 128
#define GBK 32
#define AST 40   // smem row stride (bf16 elems) — conflict-free for frag loads

__device__ __forceinline__ void mma16816(float* c, const uint32_t* a, const uint32_t* b) {
    asm volatile("mma.sync.aligned.m16n8k16.row.col.f32.bf16.bf16.f32 "
        "{%0,%1,%2,%3}, {%4,%5,%6,%7}, {%8,%9}, {%0,%1,%2,%3};"
        : "+f"(c[0]), "+f"(c[1]), "+f"(c[2]), "+f"(c[3])
        : "r"(a[0]), "r"(a[1]), "r"(a[2]), "r"(a[3]), "r"(b[0]), "r"(b[1]));
}

__global__ __launch_bounds__(256)
void gemm_kernel(const float* __restrict__ bias, float* __restrict__ out) {
    __shared__ __nv_bfloat16 As[2][GBM][AST];   // [hi/lo][m][k]
    __shared__ __nv_bfloat16 Bs[2][GBN][AST];   // [hi/lo][n][k]

    int tid  = threadIdx.x;
    int wid  = tid >> 5, lane = tid & 31;
    int wm   = wid & 1,  wn   = wid >> 1;       // warp grid 2 x 4
    int bm   = blockIdx.x * GBM;
    int bn   = blockIdx.y * GBN;
    int lq   = lane >> 2;                        // 0..7
    int lr   = lane & 3;                         // 0..3

    // gmem tile-load coords: each thread: row = tid>>2 (0..63) (+64), kq = tid&3 (8 bf16)
    int lrow = tid >> 2;
    int lkq  = tid & 3;

    float acc[4][4][4];
    #pragma unroll
    for (int mi = 0; mi < 4; mi++)
        #pragma unroll
        for (int ni = 0; ni < 4; ni++)
            #pragma unroll
            for (int q = 0; q < 4; q++) acc[mi][ni][q] = 0.f;

    // prefetch first tiles into registers
    uint4 pa[2][2], pb[2][2];
    {
        const uint4* Ah = (const uint4*)&g_Ah[(size_t)(bm + lrow) * 512 + lkq * 8];
        const uint4* Al = (const uint4*)&g_Al[(size_t)(bm + lrow) * 512 + lkq * 8];
        const uint4* Bh = (const uint4*)&g_Bh[(size_t)(bn + lrow) * 512 + lkq * 8];
        const uint4* Bl = (const uint4*)&g_Bl[(size_t)(bn + lrow) * 512 + lkq * 8];
        pa[0][0] = Ah[0]; pa[0][1] = Ah[64 * 64]; // +64 rows * 512/8 uint4
        pa[1][0] = Al[0]; pa[1][1] = Al[64 * 64];
        pb[0][0] = Bh[0]; pb[0][1] = Bh[64 * 64];
        pb[1][0] = Bl[0]; pb[1][1] = Bl[64 * 64];
    }

    for (int k0 = 0; k0 < 512; k0 += GBK) {
        // commit prefetched tiles to smem
        #pragma unroll
        for (int hl = 0; hl < 2; hl++) {
            #pragma unroll
            for (int r = 0; r < 2; r++) {
                *(uint4*)&As[hl][lrow + 64 * r][lkq * 8] = pa[hl][r];
                *(uint4*)&Bs[hl][lrow + 64 * r][lkq * 8] = pb[hl][r];
            }
        }
        __syncthreads();

        if (k0 + GBK < 512) {
            int kn = k0 + GBK;
            const uint4* Ah = (const uint4*)&g_Ah[(size_t)(bm + lrow) * 512 + kn + lkq * 8];
            const uint4* Al = (const uint4*)&g_Al[(size_t)(bm + lrow) * 512 + kn + lkq * 8];
            const uint4* Bh = (const uint4*)&g_Bh[(size_t)(bn + lrow) * 512 + kn + lkq * 8];
            const uint4* Bl = (const uint4*)&g_Bl[(size_t)(bn + lrow) * 512 + kn + lkq * 8];
            pa[0][0] = Ah[0]; pa[0][1] = Ah[64 * 64];
            pa[1][0] = Al[0]; pa[1][1] = Al[64 * 64];
            pb[0][0] = Bh[0]; pb[0][1] = Bh[64 * 64];
            pb[1][0] = Bl[0]; pb[1][1] = Bl[64 * 64];
        }

        #pragma unroll
        for (int ks = 0; ks < 2; ks++) {         // two k16 steps per BK=32
            int kb = ks * 16;
            // B fragments (hi and lo) for 4 n-tiles
            uint32_t bh[4][2], bl[4][2];
            #pragma unroll
            for (int ni = 0; ni < 4; ni++) {
                int col = wn * 32 + ni * 8 + lq;
                bh[ni][0] = *(const uint32_t*)&Bs[0][col][kb + lr * 2];
                bh[ni][1] = *(const uint32_t*)&Bs[0][col][kb + 8 + lr * 2];
                bl[ni][0] = *(const uint32_t*)&Bs[1][col][kb + lr * 2];
                bl[ni][1] = *(const uint32_t*)&Bs[1][col][kb + 8 + lr * 2];
            }
            #pragma unroll
            for (int mi = 0; mi < 4; mi++) {
                int row = wm * 64 + mi * 16 + lq;
                uint32_t a[4];
                a[0] = *(const uint32_t*)&As[0][row][kb + lr * 2];
                a[1] = *(const uint32_t*)&As[0][row + 8][kb + lr * 2];
                a[2] = *(const uint32_t*)&As[0][row][kb + 8 + lr * 2];
                a[3] = *(const uint32_t*)&As[0][row + 8][kb + 8 + lr * 2];
                #pragma unroll
                for (int ni = 0; ni < 4; ni++) mma16816(acc[mi][ni], a, bh[ni]);
                #pragma unroll
                for (int ni = 0; ni < 4; ni++) mma16816(acc[mi][ni], a, bl[ni]);
                a[0] = *(const uint32_t*)&As[1][row][kb + lr * 2];
                a[1] = *(const uint32_t*)&As[1][row + 8][kb + lr * 2];
                a[2] = *(const uint32_t*)&As[1][row][kb + 8 + lr * 2];
                a[3] = *(const uint32_t*)&As[1][row + 8][kb + 8 + lr * 2];
                #pragma unroll
                for (int ni = 0; ni < 4; ni++) mma16816(acc[mi][ni], a, bh[ni]);
            }
        }
        __syncthreads();
    }

    // epilogue: out layout (T, B, C): idx = t*(B*C) + b*C + n, with m = b*512 + t
    #pragma unroll
    for (int mi = 0; mi < 4; mi++) {
        int mrow = bm + wm * 64 + mi * 16 + lq;
        #pragma unroll
        for (int half = 0; half < 2; half++) {
            int m = mrow + half * 8;
            int b = m >> 9;
            int t = m & 511;
            float* op = out + (size_t)t * (BB * CC) + b * CC + bn;
            #pragma unroll
            for (int ni = 0; ni < 4; ni++) {
                int nloc = wn * 32 + ni * 8 + lr * 2;
                float2 v;
                v.x = acc[mi][ni][half * 2 + 0] + bias[bn + nloc];
                v.y = acc[mi][ni][half * 2 + 1] + bias[bn + nloc + 1];
                *(float2*)(op + nloc) = v;
            }
        }
    }
}

// ---------------- launch ------------------------------------------------------------
extern "C" void kernel_launch(void* const* d_in, const int* in_sizes, int n_in,
                              void* d_out, int out_size) {
    const float*         x    = (const float*)d_in[0];
    const unsigned char* mask = (const unsigned char*)d_in[1];
    const int*           tl   = (const int*)d_in[2];
    const float*         W    = (const float*)d_in[3];
    const float*         bias = (const float*)d_in[4];
    float*               out  = (float*)d_out;

    float* asum_out = out + (size_t)TMAX * BB * CC;

    phase1_kernel<<<BB, 512>>>(x, mask, tl, asum_out);
    prep_w_kernel<<<(512 * 512 + 255) / 256, 256>>>(W);
    gather_kernel<<<BB * (TMAX / TT), 128>>>(x);
    gemm_kernel<<<dim3(8192 / GBM, 512 / GBN), 256>>>(bias, out);
}

// round 5
// speedup vs baseline: 1.1957x; 1.0591x over previous
#include <cuda_runtime.h>
#include <cuda_bf16.h>
#include <math.h>
#include <stdint.h>

// Problem constants
#define SS   4096
#define BB   16
#define CC   512
#define TMAX 512

// ---------------- device scratch (static; no cudaMalloc) ----------------------------
__device__ float g_alpha[BB * SS];
__device__ float g_csum [BB * SS];
__device__ int   g_f    [BB * SS];
// A = feats bf16 split, row-major [8192][512]
__device__ __align__(16) __nv_bfloat16 g_Ah[8192 * 512];
__device__ __align__(16) __nv_bfloat16 g_Al[8192 * 512];
// B = W bf16 split, row-major [n=512][k=512] (k 511 padded to 0)
__device__ __align__(16) __nv_bfloat16 g_Bh[512 * 512];
__device__ __align__(16) __nv_bfloat16 g_Bl[512 * 512];

__constant__ int c_off[13] = {0,4096,6144,7168,7680,7936,8064,8128,8160,8176,8184,8188,8190};

// ---------------- Phase 1: alpha, alpha_sum, exact JAX-tree cumsum, fire indices ----
__device__ __forceinline__ void downsweep(float* sb, int tid) {
    for (int l = 1; l <= 12; l++) {
        int sz = SS >> l;
        int o  = c_off[l], oi = c_off[l-1];
        for (int i = tid; i < sz; i += 512)
            sb[o + i] = sb[oi + 2*i] + sb[oi + 2*i + 1];
        __syncthreads();
    }
}
__device__ __forceinline__ void upsweep(float* sb, int tid) {
    for (int l = 11; l >= 0; l--) {
        int sz = SS >> l;
        int o  = c_off[l], ou = c_off[l+1];
        for (int i = tid; i < sz; i += 512) {
            float v;
            if (i & 1)          v = sb[ou + (i >> 1)];
            else if (i == 0)    v = sb[o];
            else                v = sb[ou + (i >> 1) - 1] + sb[o + i];
            sb[o + i] = v;
        }
        __syncthreads();
    }
}

__global__ __launch_bounds__(512)
void phase1_kernel(const float* __restrict__ x,
                   const unsigned char* __restrict__ mask,
                   const int* __restrict__ tl,
                   float* __restrict__ alpha_sum_out) {
    __shared__ float sb[8192];
    int b   = blockIdx.x;
    int tid = threadIdx.x;

    for (int s = tid; s < SS; s += 512) {
        float a = mask[b * SS + s] ? -10000.0f : x[(size_t)s * (BB*CC) + b * CC + (CC - 1)];
        double sg = 1.0 / (1.0 + exp(-(double)a));
        sb[s] = (float)sg;
    }
    __syncthreads();

    downsweep(sb, tid);
    float asum = sb[c_off[12]];
    if (tid == 0) alpha_sum_out[b] = asum;
    float tlf = (float)tl[b];
    __syncthreads();

    for (int s = tid; s < SS; s += 512) {
        float sc = (sb[s] * tlf) / asum;
        sb[s] = sc;
        g_alpha[b * SS + s] = sc;
    }
    __syncthreads();

    downsweep(sb, tid);
    upsweep(sb, tid);

    for (int s = tid; s < SS; s += 512) {
        float c = sb[s];
        g_csum[b * SS + s] = c;
        g_f  [b * SS + s] = (int)floorf(c + 1e-4f);
    }
}

// ---------------- Phase 1b: W -> bf16 hi/lo, row-major [n][k] -----------------------
__global__ void prep_w_kernel(const float* __restrict__ W) {
    int i = blockIdx.x * 256 + threadIdx.x;
    if (i >= 512 * 512) return;
    int n = i >> 9;
    int k = i & 511;
    float v = (k < 511) ? W[n * 511 + k] : 0.0f;
    __nv_bfloat16 hi = __float2bfloat16(v);
    __nv_bfloat16 lo = __float2bfloat16(v - __bfloat162float(hi));
    g_Bh[i] = hi;
    g_Bl[i] = lo;
}

// ---------------- Phase 2: sparse gather, TT=8, compacted MLP-4 loads ---------------
#define TT 8

__global__ __launch_bounds__(128)
void gather_kernel(const float* __restrict__ x) {
    int blk = blockIdx.x;              // b * 64 + tg
    int b   = blk >> 6;
    int t0  = (blk & 63) * TT;
    const int*   f  = g_f     + b * SS;
    const float* al = g_alpha + b * SS;
    const float* cs = g_csum  + b * SS;

    int lo, hi;
    {
        int l = 0, r = SS;
        while (l < r) { int m = (l + r) >> 1; if (f[m] >= t0 - 1) r = m; else l = m + 1; }
        lo = l;
        l = 0; r = SS;
        while (l < r) { int m = (l + r) >> 1; if (f[m] > t0 + TT - 1) r = m; else l = m + 1; }
        hi = (l < SS - 1) ? l : SS - 1;
    }

    __shared__ float         wbuf[TT][128];
    __shared__ unsigned      wmask[128];
    __shared__ unsigned char idxs[128];
    __shared__ int           wcnt[4];
    int tid  = threadIdx.x;
    int lane = tid & 31;
    int wrp  = tid >> 5;
    int c0   = tid * 4;
    float4 acc[TT];
    #pragma unroll
    for (int tt = 0; tt < TT; tt++) acc[tt] = make_float4(0.f, 0.f, 0.f, 0.f);

    for (int base = lo; base <= hi; base += 128) {
        int s = base + tid;
        unsigned msk = 0;
        if (s <= hi) {
            int   d1   = f[s];
            int   d0   = (s == 0) ? 0 : f[s - 1];
            int   fire = d1 - d0;
            float a    = al[s];
            float c    = cs[s];
            float ex   = (fire > 1) ? (float)(fire - 1) : 0.f;
            float rw   = (fire > 0) ? (c - (float)d1) : a;
            float lw   = (a - rw) - ex;
            int   ei   = d0 + 1; if (ei > TMAX - 1) ei = TMAX - 1;
            float exc  = fminf(ex, 1.0f);
            #pragma unroll
            for (int tt = 0; tt < TT; tt++) {
                int t = t0 + tt;
                float w = 0.f;
                if (d1 == t) w += rw;
                if (d0 == t) w += lw;
                if (ei == t) w += exc;
                if (t >= d0 + 2 && t < d1) w = 1.0f;   // fill overwrite
                wbuf[tt][tid] = w;
                if (w != 0.f) msk |= (1u << tt);
            }
        }
        wmask[tid] = msk;

        // warp-ballot compaction of rows with any nonzero weight
        unsigned ball = __ballot_sync(0xffffffffu, msk != 0);
        if (lane == 0) wcnt[wrp] = __popc(ball);
        __syncthreads();
        int total = wcnt[0] + wcnt[1] + wcnt[2] + wcnt[3];
        int wo = 0;
        #pragma unroll
        for (int k = 0; k < 4; k++) if (k < wrp) wo += wcnt[k];
        if (msk) idxs[wo + __popc(ball & ((1u << lane) - 1u))] = (unsigned char)tid;
        __syncthreads();

        const float* xp = x + (size_t)base * (BB*CC) + b * CC + c0;
        int i = 0;
        for (; i + 4 <= total; i += 4) {
            int j0 = idxs[i], j1 = idxs[i+1], j2 = idxs[i+2], j3 = idxs[i+3];
            float4 v0 = *(const float4*)(xp + (size_t)j0 * (BB*CC));
            float4 v1 = *(const float4*)(xp + (size_t)j1 * (BB*CC));
            float4 v2 = *(const float4*)(xp + (size_t)j2 * (BB*CC));
            float4 v3 = *(const float4*)(xp + (size_t)j3 * (BB*CC));
            unsigned m0 = wmask[j0], m1 = wmask[j1], m2 = wmask[j2], m3 = wmask[j3];
            #pragma unroll
            for (int tt = 0; tt < TT; tt++) {
                unsigned bit = 1u << tt;
                if (m0 & bit) { float w = wbuf[tt][j0];
                    acc[tt].x += w*v0.x; acc[tt].y += w*v0.y; acc[tt].z += w*v0.z; acc[tt].w += w*v0.w; }
                if (m1 & bit) { float w = wbuf[tt][j1];
                    acc[tt].x += w*v1.x; acc[tt].y += w*v1.y; acc[tt].z += w*v1.z; acc[tt].w += w*v1.w; }
                if (m2 & bit) { float w = wbuf[tt][j2];
                    acc[tt].x += w*v2.x; acc[tt].y += w*v2.y; acc[tt].z += w*v2.z; acc[tt].w += w*v2.w; }
                if (m3 & bit) { float w = wbuf[tt][j3];
                    acc[tt].x += w*v3.x; acc[tt].y += w*v3.y; acc[tt].z += w*v3.z; acc[tt].w += w*v3.w; }
            }
        }
        for (; i < total; i++) {
            int j = idxs[i];
            float4 v = *(const float4*)(xp + (size_t)j * (BB*CC));
            unsigned m = wmask[j];
            #pragma unroll
            for (int tt = 0; tt < TT; tt++) {
                if (m & (1u << tt)) {
                    float w = wbuf[tt][j];
                    acc[tt].x += w*v.x; acc[tt].y += w*v.y; acc[tt].z += w*v.z; acc[tt].w += w*v.w;
                }
            }
        }
        __syncthreads();
    }

    // emit bf16 hi/lo rows
    #pragma unroll
    for (int tt = 0; tt < TT; tt++) {
        float4 a = acc[tt];
        if (c0 == 508) a.w = 0.f;   // channel 511 excluded
        __nv_bfloat16 h0 = __float2bfloat16(a.x), h1 = __float2bfloat16(a.y);
        __nv_bfloat16 h2 = __float2bfloat16(a.z), h3 = __float2bfloat16(a.w);
        __nv_bfloat16 l0 = __float2bfloat16(a.x - __bfloat162float(h0));
        __nv_bfloat16 l1 = __float2bfloat16(a.y - __bfloat162float(h1));
        __nv_bfloat16 l2 = __float2bfloat16(a.z - __bfloat162float(h2));
        __nv_bfloat16 l3 = __float2bfloat16(a.w - __bfloat162float(h3));
        uint2 uh, ul;
        uh.x = (unsigned)__bfloat16_as_ushort(h0) | ((unsigned)__bfloat16_as_ushort(h1) << 16);
        uh.y = (unsigned)__bfloat16_as_ushort(h2) | ((unsigned)__bfloat16_as_ushort(h3) << 16);
        ul.x = (unsigned)__bfloat16_as_ushort(l0) | ((unsigned)__bfloat16_as_ushort(l1) << 16);
        ul.y = (unsigned)__bfloat16_as_ushort(l2) | ((unsigned)__bfloat16_as_ushort(l3) << 16);
        size_t o = (size_t)(b * 512 + t0 + tt) * 512 + c0;
        *(uint2*)&g_Ah[o] = uh;
        *(uint2*)&g_Al[o] = ul;
    }
}

// ---------------- Phase 3: bf16 split GEMM on mma.sync + cp.async pipeline ----------
// M=8192, N=512, K=512. Block 128x128, BK=32, 8 warps (2x4), warp tile 64x32.
#define GBM 128
#define GBN 128
#define GBK 32
#define AST 40                       // smem row stride (bf16 elems)
#define BUF_ELEMS (128 * AST)        // one operand buffer (rows x stride)
#define SMEM_GEMM (2 * 4 * BUF_ELEMS * 2)  // 2 stages x 4 bufs x bytes = 81920

__device__ __forceinline__ uint32_t sm32(const void* p) {
    uint32_t a;
    asm("{ .reg .u64 t; cvta.to.shared.u64 t, %1; cvt.u32.u64 %0, t; }" : "=r"(a) : "l"(p));
    return a;
}
__device__ __forceinline__ void cpa16(uint32_t dst, const void* src) {
    asm volatile("cp.async.cg.shared.global [%0], [%1], 16;" :: "r"(dst), "l"(src) : "memory");
}
__device__ __forceinline__ void mma16816(float* c, const uint32_t* a, const uint32_t* b) {
    asm volatile("mma.sync.aligned.m16n8k16.row.col.f32.bf16.bf16.f32 "
        "{%0,%1,%2,%3}, {%4,%5,%6,%7}, {%8,%9}, {%0,%1,%2,%3};"
        : "+f"(c[0]), "+f"(c[1]), "+f"(c[2]), "+f"(c[3])
        : "r"(a[0]), "r"(a[1]), "r"(a[2]), "r"(a[3]), "r"(b[0]), "r"(b[1]));
}

extern __shared__ __align__(16) __nv_bfloat16 dsm[];

__global__ __launch_bounds__(256, 2)
void gemm_kernel(const float* __restrict__ bias, float* __restrict__ out) {
    int tid  = threadIdx.x;
    int wid  = tid >> 5, lane = tid & 31;
    int wm   = wid & 1,  wn   = wid >> 1;       // warp grid 2 x 4
    int bm   = blockIdx.x * GBM;
    int bn   = blockIdx.y * GBN;
    int lq   = lane >> 2;                        // 0..7
    int lr   = lane & 3;                         // 0..3

    // copy mapping: 256 threads, each does 2x16B per buffer, 4 buffers
    int crow = tid >> 1;                         // 0..127
    int ckq  = (tid & 1) * 16;                   // k elem offset: 0 or 16

    uint32_t smb = sm32(dsm);

    float acc[4][4][4];
    #pragma unroll
    for (int mi = 0; mi < 4; mi++)
        #pragma unroll
        for (int ni = 0; ni < 4; ni++)
            #pragma unroll
            for (int q = 0; q < 4; q++) acc[mi][ni][q] = 0.f;

    const __nv_bfloat16* gA = g_Ah + (size_t)(bm + crow) * 512 + ckq;
    const __nv_bfloat16* gAl = g_Al + (size_t)(bm + crow) * 512 + ckq;
    const __nv_bfloat16* gB = g_Bh + (size_t)(bn + crow) * 512 + ckq;
    const __nv_bfloat16* gBl = g_Bl + (size_t)(bn + crow) * 512 + ckq;

    #define ISSUE_STAGE(c, st) do {                                              \
        int k0 = (c) * GBK;                                                      \
        uint32_t dbase = smb + (uint32_t)((((st)*4)*128 + crow)*AST + ckq) * 2;   \
        cpa16(dbase,                        gA  + k0);                            \
        cpa16(dbase + 16,                   gA  + k0 + 8);                        \
        cpa16(dbase + BUF_ELEMS*2,          gAl + k0);                            \
        cpa16(dbase + BUF_ELEMS*2 + 16,     gAl + k0 + 8);                        \
        cpa16(dbase + 2*BUF_ELEMS*2,        gB  + k0);                            \
        cpa16(dbase + 2*BUF_ELEMS*2 + 16,   gB  + k0 + 8);                        \
        cpa16(dbase + 3*BUF_ELEMS*2,        gBl + k0);                            \
        cpa16(dbase + 3*BUF_ELEMS*2 + 16,   gBl + k0 + 8);                        \
    } while (0)

    ISSUE_STAGE(0, 0);
    asm volatile("cp.async.commit_group;" ::: "memory");
    ISSUE_STAGE(1, 1);
    asm volatile("cp.async.commit_group;" ::: "memory");

    for (int c = 0; c < 16; c++) {
        int st = c & 1;
        asm volatile("cp.async.wait_group 1;" ::: "memory");
        __syncthreads();

        const __nv_bfloat16* PAh = dsm + (size_t)(st*4 + 0) * BUF_ELEMS;
        const __nv_bfloat16* PAl = dsm + (size_t)(st*4 + 1) * BUF_ELEMS;
        const __nv_bfloat16* PBh = dsm + (size_t)(st*4 + 2) * BUF_ELEMS;
        const __nv_bfloat16* PBl = dsm + (size_t)(st*4 + 3) * BUF_ELEMS;

        #pragma unroll
        for (int ks = 0; ks < 2; ks++) {         // two k16 steps per BK=32
            int kb = ks * 16;
            uint32_t bh[4][2], bl[4][2];
            #pragma unroll
            for (int ni = 0; ni < 4; ni++) {
                int col = wn * 32 + ni * 8 + lq;
                bh[ni][0] = *(const uint32_t*)&PBh[col*AST + kb + lr * 2];
                bh[ni][1] = *(const uint32_t*)&PBh[col*AST + kb + 8 + lr * 2];
                bl[ni][0] = *(const uint32_t*)&PBl[col*AST + kb + lr * 2];
                bl[ni][1] = *(const uint32_t*)&PBl[col*AST + kb + 8 + lr * 2];
            }
            #pragma unroll
            for (int mi = 0; mi < 4; mi++) {
                int row = wm * 64 + mi * 16 + lq;
                uint32_t a[4];
                a[0] = *(const uint32_t*)&PAh[row*AST + kb + lr * 2];
                a[1] = *(const uint32_t*)&PAh[(row + 8)*AST + kb + lr * 2];
                a[2] = *(const uint32_t*)&PAh[row*AST + kb + 8 + lr * 2];
                a[3] = *(const uint32_t*)&PAh[(row + 8)*AST + kb + 8 + lr * 2];
                #pragma unroll
                for (int ni = 0; ni < 4; ni++) mma16816(acc[mi][ni], a, bh[ni]);
                #pragma unroll
                for (int ni = 0; ni < 4; ni++) mma16816(acc[mi][ni], a, bl[ni]);
                a[0] = *(const uint32_t*)&PAl[row*AST + kb + lr * 2];
                a[1] = *(const uint32_t*)&PAl[(row + 8)*AST + kb + lr * 2];
                a[2] = *(const uint32_t*)&PAl[row*AST + kb + 8 + lr * 2];
                a[3] = *(const uint32_t*)&PAl[(row + 8)*AST + kb + 8 + lr * 2];
                #pragma unroll
                for (int ni = 0; ni < 4; ni++) mma16816(acc[mi][ni], a, bh[ni]);
            }
        }
        __syncthreads();

        if (c + 2 < 16) ISSUE_STAGE(c + 2, st);
        asm volatile("cp.async.commit_group;" ::: "memory");
    }

    // epilogue: out layout (T, B, C): idx = t*(B*C) + b*C + n, with m = b*512 + t
    #pragma unroll
    for (int mi = 0; mi < 4; mi++) {
        int mrow = bm + wm * 64 + mi * 16 + lq;
        #pragma unroll
        for (int half = 0; half < 2; half++) {
            int m = mrow + half * 8;
            int b = m >> 9;
            int t = m & 511;
            float* op = out + (size_t)t * (BB * CC) + b * CC + bn;
            #pragma unroll
            for (int ni = 0; ni < 4; ni++) {
                int nloc = wn * 32 + ni * 8 + lr * 2;
                float2 v;
                v.x = acc[mi][ni][half * 2 + 0] + bias[bn + nloc];
                v.y = acc[mi][ni][half * 2 + 1] + bias[bn + nloc + 1];
                *(float2*)(op + nloc) = v;
            }
        }
    }
}

// ---------------- launch ------------------------------------------------------------
extern "C" void kernel_launch(void* const* d_in, const int* in_sizes, int n_in,
                              void* d_out, int out_size) {
    const float*         x    = (const float*)d_in[0];
    const unsigned char* mask = (const unsigned char*)d_in[1];
    const int*           tl   = (const int*)d_in[2];
    const float*         W    = (const float*)d_in[3];
    const float*         bias = (const float*)d_in[4];
    float*               out  = (float*)d_out;

    float* asum_out = out + (size_t)TMAX * BB * CC;

    cudaFuncSetAttribute(gemm_kernel, cudaFuncAttributeMaxDynamicSharedMemorySize, SMEM_GEMM);

    phase1_kernel<<<BB, 512>>>(x, mask, tl, asum_out);
    prep_w_kernel<<<(512 * 512 + 255) / 256, 256>>>(W);
    gather_kernel<<<BB * (TMAX / TT), 128>>>(x);
    gemm_kernel<<<dim3(8192 / GBM, 512 / GBN), 256, SMEM_GEMM>>>(bias, out);
}

// round 6
// speedup vs baseline: 1.6475x; 1.3779x over previous
#include <cuda_runtime.h>
#include <cuda_bf16.h>
#include <math.h>
#include <stdint.h>

// Problem constants
#define SS   4096
#define BB   16
#define CC   512
#define TMAX 512

// ---------------- device scratch (static; no cudaMalloc) ----------------------------
__device__ float g_sig  [BB * SS];          // raw sigmoid
__device__ float g_alpha[BB * SS];          // scaled alpha
__device__ float g_csum [BB * SS];
__device__ int   g_f    [BB * SS];
__device__ __align__(16) __nv_bfloat16 g_Ah[8192 * 512];
__device__ __align__(16) __nv_bfloat16 g_Al[8192 * 512];
__device__ __align__(16) __nv_bfloat16 g_Bh[512 * 512];
__device__ __align__(16) __nv_bfloat16 g_Bl[512 * 512];

__constant__ int c_off[13] = {0,4096,6144,7168,7680,7936,8064,8128,8160,8176,8184,8188,8190};

// ---------------- Phase 1a: fp64 sigmoid spread over the whole chip -----------------
__global__ __launch_bounds__(256)
void sigmoid_kernel(const float* __restrict__ x, const unsigned char* __restrict__ mask) {
    int i = blockIdx.x * 256 + threadIdx.x;    // i = b*SS + s
    int b = i >> 12;
    int s = i & (SS - 1);
    float a = mask[i] ? -10000.0f : x[(size_t)s * (BB*CC) + b * CC + (CC - 1)];
    double sg = 1.0 / (1.0 + exp(-(double)a));
    g_sig[i] = (float)sg;
}

// ---------------- Phase 1b: fp32 reduce + exact JAX-tree cumsum + fire indices ------
__device__ __forceinline__ void downsweep(float* sb, int tid) {
    for (int l = 1; l <= 12; l++) {
        int sz = SS >> l;
        int o  = c_off[l], oi = c_off[l-1];
        for (int i = tid; i < sz; i += 512)
            sb[o + i] = sb[oi + 2*i] + sb[oi + 2*i + 1];
        __syncthreads();
    }
}
__device__ __forceinline__ void upsweep(float* sb, int tid) {
    for (int l = 11; l >= 0; l--) {
        int sz = SS >> l;
        int o  = c_off[l], ou = c_off[l+1];
        for (int i = tid; i < sz; i += 512) {
            float v;
            if (i & 1)          v = sb[ou + (i >> 1)];
            else if (i == 0)    v = sb[o];
            else                v = sb[ou + (i >> 1) - 1] + sb[o + i];
            sb[o + i] = v;
        }
        __syncthreads();
    }
}

__global__ __launch_bounds__(512)
void scan_kernel(const int* __restrict__ tl, float* __restrict__ alpha_sum_out) {
    __shared__ float sb[8192];
    int b   = blockIdx.x;
    int tid = threadIdx.x;

    for (int s = tid; s < SS; s += 512) sb[s] = g_sig[b * SS + s];
    __syncthreads();

    downsweep(sb, tid);
    float asum = sb[c_off[12]];
    if (tid == 0) alpha_sum_out[b] = asum;
    float tlf = (float)tl[b];
    __syncthreads();

    for (int s = tid; s < SS; s += 512) {
        float sc = (sb[s] * tlf) / asum;
        sb[s] = sc;
        g_alpha[b * SS + s] = sc;
    }
    __syncthreads();

    downsweep(sb, tid);
    upsweep(sb, tid);

    for (int s = tid; s < SS; s += 512) {
        float c = sb[s];
        g_csum[b * SS + s] = c;
        g_f  [b * SS + s] = (int)floorf(c + 1e-4f);
    }
}

// ---------------- Phase 1c: W -> bf16 hi/lo, row-major [n][k] -----------------------
__global__ void prep_w_kernel(const float* __restrict__ W) {
    int i = blockIdx.x * 256 + threadIdx.x;
    if (i >= 512 * 512) return;
    int n = i >> 9;
    int k = i & 511;
    float v = (k < 511) ? W[n * 511 + k] : 0.0f;
    __nv_bfloat16 hi = __float2bfloat16(v);
    __nv_bfloat16 lo = __float2bfloat16(v - __bfloat162float(hi));
    g_Bh[i] = hi;
    g_Bl[i] = lo;
}

// ---------------- Phase 2: sparse gather, TT=8, channel-split (2 blocks/row-group) --
#define TT 8

__global__ __launch_bounds__(128)
void gather_kernel(const float* __restrict__ x) {
    int blk   = blockIdx.x;            // b * 128 + tg*2 + chalf
    int b     = blk >> 7;
    int rest  = blk & 127;
    int tg    = rest >> 1;
    int chalf = rest & 1;
    int t0    = tg * TT;
    const int*   f  = g_f     + b * SS;
    const float* al = g_alpha + b * SS;
    const float* cs = g_csum  + b * SS;

    int lo, hi;
    {
        int l = 0, r = SS;
        while (l < r) { int m = (l + r) >> 1; if (f[m] >= t0 - 1) r = m; else l = m + 1; }
        lo = l;
        l = 0; r = SS;
        while (l < r) { int m = (l + r) >> 1; if (f[m] > t0 + TT - 1) r = m; else l = m + 1; }
        hi = (l < SS - 1) ? l : SS - 1;
    }

    __shared__ float    wbuf[TT][128];
    __shared__ unsigned wmask[128];
    int tid = threadIdx.x;
    int c0  = chalf * 256 + tid * 2;   // global channel of .x
    float2 acc[TT];
    #pragma unroll
    for (int tt = 0; tt < TT; tt++) acc[tt] = make_float2(0.f, 0.f);

    for (int base = lo; base <= hi; base += 128) {
        int s = base + tid;
        unsigned msk = 0;
        if (s <= hi) {
            int   d1   = f[s];
            int   d0   = (s == 0) ? 0 : f[s - 1];
            int   fire = d1 - d0;
            float a    = al[s];
            float c    = cs[s];
            float ex   = (fire > 1) ? (float)(fire - 1) : 0.f;
            float rw   = (fire > 0) ? (c - (float)d1) : a;
            float lw   = (a - rw) - ex;
            int   ei   = d0 + 1; if (ei > TMAX - 1) ei = TMAX - 1;
            float exc  = fminf(ex, 1.0f);
            #pragma unroll
            for (int tt = 0; tt < TT; tt++) {
                int t = t0 + tt;
                float w = 0.f;
                if (d1 == t) w += rw;
                if (d0 == t) w += lw;
                if (ei == t) w += exc;
                if (t >= d0 + 2 && t < d1) w = 1.0f;   // fill overwrite
                wbuf[tt][tid] = w;
                if (w != 0.f) msk |= (1u << tt);
            }
        } else {
            #pragma unroll
            for (int tt = 0; tt < TT; tt++) wbuf[tt][tid] = 0.f;
        }
        wmask[tid] = msk;
        __syncthreads();

        int n = hi - base + 1; if (n > 128) n = 128;
        const float* xp = x + (size_t)base * (BB*CC) + b * CC + c0;
        int j = 0;
        for (; j + 4 <= n; j += 4) {
            float2 v0 = *(const float2*)(xp + (size_t)(j+0) * (BB*CC));
            float2 v1 = *(const float2*)(xp + (size_t)(j+1) * (BB*CC));
            float2 v2 = *(const float2*)(xp + (size_t)(j+2) * (BB*CC));
            float2 v3 = *(const float2*)(xp + (size_t)(j+3) * (BB*CC));
            unsigned m0 = wmask[j], m1 = wmask[j+1], m2 = wmask[j+2], m3 = wmask[j+3];
            #pragma unroll
            for (int tt = 0; tt < TT; tt++) {
                unsigned bit = 1u << tt;
                if (m0 & bit) { float w = wbuf[tt][j+0]; acc[tt].x += w*v0.x; acc[tt].y += w*v0.y; }
                if (m1 & bit) { float w = wbuf[tt][j+1]; acc[tt].x += w*v1.x; acc[tt].y += w*v1.y; }
                if (m2 & bit) { float w = wbuf[tt][j+2]; acc[tt].x += w*v2.x; acc[tt].y += w*v2.y; }
                if (m3 & bit) { float w = wbuf[tt][j+3]; acc[tt].x += w*v3.x; acc[tt].y += w*v3.y; }
            }
        }
        for (; j < n; j++) {
            unsigned m = wmask[j];
            if (!m) continue;
            float2 v = *(const float2*)(xp + (size_t)j * (BB*CC));
            #pragma unroll
            for (int tt = 0; tt < TT; tt++) {
                if (m & (1u << tt)) { float w = wbuf[tt][j]; acc[tt].x += w*v.x; acc[tt].y += w*v.y; }
            }
        }
        __syncthreads();
    }

    // emit bf16 hi/lo
    #pragma unroll
    for (int tt = 0; tt < TT; tt++) {
        float2 a = acc[tt];
        if (c0 == 510) a.y = 0.f;   // channel 511 excluded
        __nv_bfloat16 h0 = __float2bfloat16(a.x), h1 = __float2bfloat16(a.y);
        __nv_bfloat16 l0 = __float2bfloat16(a.x - __bfloat162float(h0));
        __nv_bfloat16 l1 = __float2bfloat16(a.y - __bfloat162float(h1));
        uint32_t uh = (unsigned)__bfloat16_as_ushort(h0) | ((unsigned)__bfloat16_as_ushort(h1) << 16);
        uint32_t ul = (unsigned)__bfloat16_as_ushort(l0) | ((unsigned)__bfloat16_as_ushort(l1) << 16);
        size_t o = (size_t)(b * 512 + t0 + tt) * 512 + c0;
        *(uint32_t*)&g_Ah[o] = uh;
        *(uint32_t*)&g_Al[o] = ul;
    }
}

// ---------------- Phase 3: bf16 split GEMM, mma.sync + ldmatrix + cp.async ----------
#define GBM 128
#define GBN 128
#define GBK 32
#define AST 40
#define BUF_ELEMS (128 * AST)
#define SMEM_GEMM (2 * 4 * BUF_ELEMS * 2)   // 81920

__device__ __forceinline__ uint32_t sm32(const void* p) {
    uint32_t a;
    asm("{ .reg .u64 t; cvta.to.shared.u64 t, %1; cvt.u32.u64 %0, t; }" : "=r"(a) : "l"(p));
    return a;
}
__device__ __forceinline__ void cpa16(uint32_t dst, const void* src) {
    asm volatile("cp.async.cg.shared.global [%0], [%1], 16;" :: "r"(dst), "l"(src) : "memory");
}
__device__ __forceinline__ void ldsm4(uint32_t* r, uint32_t addr) {
    asm volatile("ldmatrix.sync.aligned.m8n8.x4.shared.b16 {%0,%1,%2,%3}, [%4];"
        : "=r"(r[0]), "=r"(r[1]), "=r"(r[2]), "=r"(r[3]) : "r"(addr));
}
__device__ __forceinline__ void mma16816(float* c, const uint32_t* a, const uint32_t* b) {
    asm volatile("mma.sync.aligned.m16n8k16.row.col.f32.bf16.bf16.f32 "
        "{%0,%1,%2,%3}, {%4,%5,%6,%7}, {%8,%9}, {%0,%1,%2,%3};"
        : "+f"(c[0]), "+f"(c[1]), "+f"(c[2]), "+f"(c[3])
        : "r"(a[0]), "r"(a[1]), "r"(a[2]), "r"(a[3]), "r"(b[0]), "r"(b[1]));
}

extern __shared__ __align__(16) __nv_bfloat16 dsm[];

__global__ __launch_bounds__(256, 2)
void gemm_kernel(const float* __restrict__ bias, float* __restrict__ out) {
    int tid  = threadIdx.x;
    int wid  = tid >> 5, lane = tid & 31;
    int wm   = wid & 1,  wn   = wid >> 1;       // warp grid 2 x 4
    int bm   = blockIdx.x * GBM;
    int bn   = blockIdx.y * GBN;
    int lq   = lane >> 2;
    int lr   = lane & 3;

    int crow = tid >> 1;
    int ckq  = (tid & 1) * 16;

    uint32_t smb = sm32(dsm);

    // ldmatrix per-lane address components
    int arow = (lane & 7) + ((lane >> 3) & 1) * 8;   // A: row within 16
    int akc  = (lane >> 4) * 8;                      // A: k offset 0/8
    int bnof = (lane >> 4) * 8 + (lane & 7);         // B: n within 16
    int bkc  = ((lane >> 3) & 1) * 8;                // B: k offset 0/8

    float acc[4][4][4];
    #pragma unroll
    for (int mi = 0; mi < 4; mi++)
        #pragma unroll
        for (int ni = 0; ni < 4; ni++)
            #pragma unroll
            for (int q = 0; q < 4; q++) acc[mi][ni][q] = 0.f;

    const __nv_bfloat16* gA  = g_Ah + (size_t)(bm + crow) * 512 + ckq;
    const __nv_bfloat16* gAl = g_Al + (size_t)(bm + crow) * 512 + ckq;
    const __nv_bfloat16* gB  = g_Bh + (size_t)(bn + crow) * 512 + ckq;
    const __nv_bfloat16* gBl = g_Bl + (size_t)(bn + crow) * 512 + ckq;

    #define ISSUE_STAGE(c, st) do {                                              \
        int k0 = (c) * GBK;                                                      \
        uint32_t dbase = smb + (uint32_t)((((st)*4)*128 + crow)*AST + ckq) * 2;   \
        cpa16(dbase,                        gA  + k0);                            \
        cpa16(dbase + 16,                   gA  + k0 + 8);                        \
        cpa16(dbase + BUF_ELEMS*2,          gAl + k0);                            \
        cpa16(dbase + BUF_ELEMS*2 + 16,     gAl + k0 + 8);                        \
        cpa16(dbase + 2*BUF_ELEMS*2,        gB  + k0);                            \
        cpa16(dbase + 2*BUF_ELEMS*2 + 16,   gB  + k0 + 8);                        \
        cpa16(dbase + 3*BUF_ELEMS*2,        gBl + k0);                            \
        cpa16(dbase + 3*BUF_ELEMS*2 + 16,   gBl + k0 + 8);                        \
    } while (0)

    ISSUE_STAGE(0, 0);
    asm volatile("cp.async.commit_group;" ::: "memory");
    ISSUE_STAGE(1, 1);
    asm volatile("cp.async.commit_group;" ::: "memory");

    for (int c = 0; c < 16; c++) {
        int st = c & 1;
        asm volatile("cp.async.wait_group 1;" ::: "memory");
        __syncthreads();

        uint32_t sAh = smb + (uint32_t)((st*4 + 0) * BUF_ELEMS) * 2;
        uint32_t sAl = smb + (uint32_t)((st*4 + 1) * BUF_ELEMS) * 2;
        uint32_t sBh = smb + (uint32_t)((st*4 + 2) * BUF_ELEMS) * 2;
        uint32_t sBl = smb + (uint32_t)((st*4 + 3) * BUF_ELEMS) * 2;

        #pragma unroll
        for (int ks = 0; ks < 2; ks++) {
            int kb = ks * 16;
            // B fragments via ldmatrix: 2 x4 loads per hi/lo cover 4 n-tiles
            uint32_t bh[4][2], bl[4][2];
            #pragma unroll
            for (int nip = 0; nip < 2; nip++) {
                int ncol = wn * 32 + nip * 16 + bnof;
                uint32_t off = (uint32_t)(ncol * AST + kb + bkc) * 2;
                uint32_t r[4];
                ldsm4(r, sBh + off);
                bh[nip*2+0][0] = r[0]; bh[nip*2+0][1] = r[1];
                bh[nip*2+1][0] = r[2]; bh[nip*2+1][1] = r[3];
                ldsm4(r, sBl + off);
                bl[nip*2+0][0] = r[0]; bl[nip*2+0][1] = r[1];
                bl[nip*2+1][0] = r[2]; bl[nip*2+1][1] = r[3];
            }
            #pragma unroll
            for (int mi = 0; mi < 4; mi++) {
                int row = wm * 64 + mi * 16 + arow;
                uint32_t off = (uint32_t)(row * AST + kb + akc) * 2;
                uint32_t a[4];
                ldsm4(a, sAh + off);
                #pragma unroll
                for (int ni = 0; ni < 4; ni++) mma16816(acc[mi][ni], a, bh[ni]);
                #pragma unroll
                for (int ni = 0; ni < 4; ni++) mma16816(acc[mi][ni], a, bl[ni]);
                ldsm4(a, sAl + off);
                #pragma unroll
                for (int ni = 0; ni < 4; ni++) mma16816(acc[mi][ni], a, bh[ni]);
            }
        }
        __syncthreads();

        if (c + 2 < 16) ISSUE_STAGE(c + 2, st);
        asm volatile("cp.async.commit_group;" ::: "memory");
    }

    // epilogue: out layout (T, B, C): idx = t*(B*C) + b*C + n, with m = b*512 + t
    #pragma unroll
    for (int mi = 0; mi < 4; mi++) {
        int mrow = bm + wm * 64 + mi * 16 + lq;
        #pragma unroll
        for (int half = 0; half < 2; half++) {
            int m = mrow + half * 8;
            int b = m >> 9;
            int t = m & 511;
            float* op = out + (size_t)t * (BB * CC) + b * CC + bn;
            #pragma unroll
            for (int ni = 0; ni < 4; ni++) {
                int nloc = wn * 32 + ni * 8 + lr * 2;
                float2 v;
                v.x = acc[mi][ni][half * 2 + 0] + bias[bn + nloc];
                v.y = acc[mi][ni][half * 2 + 1] + bias[bn + nloc + 1];
                *(float2*)(op + nloc) = v;
            }
        }
    }
}

// ---------------- launch ------------------------------------------------------------
extern "C" void kernel_launch(void* const* d_in, const int* in_sizes, int n_in,
                              void* d_out, int out_size) {
    const float*         x    = (const float*)d_in[0];
    const unsigned char* mask = (const unsigned char*)d_in[1];
    const int*           tl   = (const int*)d_in[2];
    const float*         W    = (const float*)d_in[3];
    const float*         bias = (const float*)d_in[4];
    float*               out  = (float*)d_out;

    float* asum_out = out + (size_t)TMAX * BB * CC;

    cudaFuncSetAttribute(gemm_kernel, cudaFuncAttributeMaxDynamicSharedMemorySize, SMEM_GEMM);

    sigmoid_kernel<<<(BB * SS) / 256, 256>>>(x, mask);
    scan_kernel<<<BB, 512>>>(tl, asum_out);
    prep_w_kernel<<<(512 * 512 + 255) / 256, 256>>>(W);
    gather_kernel<<<BB * 64 * 2, 128>>>(x);
    gemm_kernel<<<dim3(8192 / GBM, 512 / GBN), 256, SMEM_GEMM>>>(bias, out);
}

// round 7
// speedup vs baseline: 1.8204x; 1.1050x over previous
#include <cuda_runtime.h>
#include <cuda_bf16.h>
#include <math.h>
#include <stdint.h>

// Problem constants
#define SS   4096
#define BB   16
#define CC   512
#define TMAX 512

// ---------------- device scratch (static; no cudaMalloc) ----------------------------
__device__ float g_sig  [BB * SS];          // raw sigmoid
__device__ float g_alpha[BB * SS];          // scaled alpha
__device__ float g_csum [BB * SS];
__device__ int   g_f    [BB * SS];
__device__ __align__(16) __nv_bfloat16 g_Ah[8192 * 512];
__device__ __align__(16) __nv_bfloat16 g_Al[8192 * 512];
__device__ __align__(16) __nv_bfloat16 g_Bh[512 * 512];
__device__ __align__(16) __nv_bfloat16 g_Bl[512 * 512];

__constant__ int c_off[13] = {0,4096,6144,7168,7680,7936,8064,8128,8160,8176,8184,8188,8190};

// ---------------- Phase 1a: fp64 sigmoid spread over the whole chip -----------------
__global__ __launch_bounds__(256)
void sigmoid_kernel(const float* __restrict__ x, const unsigned char* __restrict__ mask) {
    int i = blockIdx.x * 256 + threadIdx.x;    // i = b*SS + s
    int b = i >> 12;
    int s = i & (SS - 1);
    float a = mask[i] ? -10000.0f : x[(size_t)s * (BB*CC) + b * CC + (CC - 1)];
    double sg = 1.0 / (1.0 + exp(-(double)a));
    g_sig[i] = (float)sg;
}

// ---------------- Phase 1b: fp32 reduce + exact JAX-tree cumsum + fire indices ------
__device__ __forceinline__ void downsweep(float* sb, int tid) {
    for (int l = 1; l <= 12; l++) {
        int sz = SS >> l;
        int o  = c_off[l], oi = c_off[l-1];
        for (int i = tid; i < sz; i += 512)
            sb[o + i] = sb[oi + 2*i] + sb[oi + 2*i + 1];
        __syncthreads();
    }
}
__device__ __forceinline__ void upsweep(float* sb, int tid) {
    for (int l = 11; l >= 0; l--) {
        int sz = SS >> l;
        int o  = c_off[l], ou = c_off[l+1];
        for (int i = tid; i < sz; i += 512) {
            float v;
            if (i & 1)          v = sb[ou + (i >> 1)];
            else if (i == 0)    v = sb[o];
            else                v = sb[ou + (i >> 1) - 1] + sb[o + i];
            sb[o + i] = v;
        }
        __syncthreads();
    }
}

__global__ __launch_bounds__(512)
void scan_kernel(const int* __restrict__ tl, float* __restrict__ alpha_sum_out) {
    __shared__ float sb[8192];
    int b   = blockIdx.x;
    int tid = threadIdx.x;

    for (int s = tid; s < SS; s += 512) sb[s] = g_sig[b * SS + s];
    __syncthreads();

    downsweep(sb, tid);
    float asum = sb[c_off[12]];
    if (tid == 0) alpha_sum_out[b] = asum;
    float tlf = (float)tl[b];
    __syncthreads();

    for (int s = tid; s < SS; s += 512) {
        float sc = (sb[s] * tlf) / asum;
        sb[s] = sc;
        g_alpha[b * SS + s] = sc;
    }
    __syncthreads();

    downsweep(sb, tid);
    upsweep(sb, tid);

    for (int s = tid; s < SS; s += 512) {
        float c = sb[s];
        g_csum[b * SS + s] = c;
        g_f  [b * SS + s] = (int)floorf(c + 1e-4f);
    }
}

// ---------------- Phase 1c: W -> bf16 hi/lo, row-major [n][k] -----------------------
__global__ void prep_w_kernel(const float* __restrict__ W) {
    int i = blockIdx.x * 256 + threadIdx.x;
    if (i >= 512 * 512) return;
    int n = i >> 9;
    int k = i & 511;
    float v = (k < 511) ? W[n * 511 + k] : 0.0f;
    __nv_bfloat16 hi = __float2bfloat16(v);
    __nv_bfloat16 lo = __float2bfloat16(v - __bfloat162float(hi));
    g_Bh[i] = hi;
    g_Bl[i] = lo;
}

// ---------------- Phase 2: sparse gather, TT=8, pipelined MLP-16 loads --------------
#define TT 8

__global__ __launch_bounds__(128)
void gather_kernel(const float* __restrict__ x) {
    int blk   = blockIdx.x;            // b * 128 + tg*2 + chalf
    int b     = blk >> 7;
    int rest  = blk & 127;
    int tg    = rest >> 1;
    int chalf = rest & 1;
    int t0    = tg * TT;
    const int*   f  = g_f     + b * SS;
    const float* al = g_alpha + b * SS;
    const float* cs = g_csum  + b * SS;

    int lo, hi;
    {
        int l = 0, r = SS;
        while (l < r) { int m = (l + r) >> 1; if (f[m] >= t0 - 1) r = m; else l = m + 1; }
        lo = l;
        l = 0; r = SS;
        while (l < r) { int m = (l + r) >> 1; if (f[m] > t0 + TT - 1) r = m; else l = m + 1; }
        hi = (l < SS - 1) ? l : SS - 1;
    }

    __shared__ float wbuf[TT][144];    // [128..143] stays zero (prefetch overrun pad)
    int tid = threadIdx.x;
    int c0  = chalf * 256 + tid * 2;   // global channel of .x
    float2 acc[TT];
    #pragma unroll
    for (int tt = 0; tt < TT; tt++) acc[tt] = make_float2(0.f, 0.f);

    if (tid < 16) {
        #pragma unroll
        for (int tt = 0; tt < TT; tt++) wbuf[tt][128 + tid] = 0.f;
    }

    for (int base = lo; base <= hi; base += 128) {
        int s = base + tid;
        if (s <= hi) {
            int   d1   = f[s];
            int   d0   = (s == 0) ? 0 : f[s - 1];
            int   fire = d1 - d0;
            float a    = al[s];
            float c    = cs[s];
            float ex   = (fire > 1) ? (float)(fire - 1) : 0.f;
            float rw   = (fire > 0) ? (c - (float)d1) : a;
            float lw   = (a - rw) - ex;
            int   ei   = d0 + 1; if (ei > TMAX - 1) ei = TMAX - 1;
            float exc  = fminf(ex, 1.0f);
            #pragma unroll
            for (int tt = 0; tt < TT; tt++) {
                int t = t0 + tt;
                float w = 0.f;
                if (d1 == t) w += rw;
                if (d0 == t) w += lw;
                if (ei == t) w += exc;
                if (t >= d0 + 2 && t < d1) w = 1.0f;   // fill overwrite
                wbuf[tt][tid] = w;
            }
        } else {
            #pragma unroll
            for (int tt = 0; tt < TT; tt++) wbuf[tt][tid] = 0.f;
        }
        __syncthreads();

        int n = hi - base + 1; if (n > 128) n = 128;
        const float* xp = x + (size_t)base * (BB*CC) + b * CC + c0;

        // software-pipelined: 8 rows in flight + 8 prefetched (clamped, weight=0 pad)
        float2 v[8];
        #pragma unroll
        for (int q = 0; q < 8; q++) {
            int r = q < n ? q : n - 1;
            v[q] = *(const float2*)(xp + (size_t)r * (BB*CC));
        }
        for (int j = 0; j < n; j += 8) {
            float2 nv[8];
            #pragma unroll
            for (int q = 0; q < 8; q++) {
                int r = j + 8 + q; r = r < n ? r : n - 1;
                nv[q] = *(const float2*)(xp + (size_t)r * (BB*CC));
            }
            #pragma unroll
            for (int q = 0; q < 8; q++) {
                #pragma unroll
                for (int tt = 0; tt < TT; tt++) {
                    float w = wbuf[tt][j + q];
                    acc[tt].x += w * v[q].x;
                    acc[tt].y += w * v[q].y;
                }
            }
            #pragma unroll
            for (int q = 0; q < 8; q++) v[q] = nv[q];
        }
        __syncthreads();
    }

    // emit bf16 hi/lo
    #pragma unroll
    for (int tt = 0; tt < TT; tt++) {
        float2 a = acc[tt];
        if (c0 == 510) a.y = 0.f;   // channel 511 excluded
        __nv_bfloat16 h0 = __float2bfloat16(a.x), h1 = __float2bfloat16(a.y);
        __nv_bfloat16 l0 = __float2bfloat16(a.x - __bfloat162float(h0));
        __nv_bfloat16 l1 = __float2bfloat16(a.y - __bfloat162float(h1));
        uint32_t uh = (unsigned)__bfloat16_as_ushort(h0) | ((unsigned)__bfloat16_as_ushort(h1) << 16);
        uint32_t ul = (unsigned)__bfloat16_as_ushort(l0) | ((unsigned)__bfloat16_as_ushort(l1) << 16);
        size_t o = (size_t)(b * 512 + t0 + tt) * 512 + c0;
        *(uint32_t*)&g_Ah[o] = uh;
        *(uint32_t*)&g_Al[o] = ul;
    }
}

// ---------------- Phase 3: bf16 split GEMM, mma.sync + ldmatrix + cp.async ----------
#define GBM 128
#define GBN 128
#define GBK 32
#define AST 40
#define BUF_ELEMS (128 * AST)
#define SMEM_GEMM (2 * 4 * BUF_ELEMS * 2)   // 81920

__device__ __forceinline__ uint32_t sm32(const void* p) {
    uint32_t a;
    asm("{ .reg .u64 t; cvta.to.shared.u64 t, %1; cvt.u32.u64 %0, t; }" : "=r"(a) : "l"(p));
    return a;
}
__device__ __forceinline__ void cpa16(uint32_t dst, const void* src) {
    asm volatile("cp.async.cg.shared.global [%0], [%1], 16;" :: "r"(dst), "l"(src) : "memory");
}
__device__ __forceinline__ void ldsm4(uint32_t* r, uint32_t addr) {
    asm volatile("ldmatrix.sync.aligned.m8n8.x4.shared.b16 {%0,%1,%2,%3}, [%4];"
        : "=r"(r[0]), "=r"(r[1]), "=r"(r[2]), "=r"(r[3]) : "r"(addr));
}
__device__ __forceinline__ void mma16816(float* c, const uint32_t* a, const uint32_t* b) {
    asm volatile("mma.sync.aligned.m16n8k16.row.col.f32.bf16.bf16.f32 "
        "{%0,%1,%2,%3}, {%4,%5,%6,%7}, {%8,%9}, {%0,%1,%2,%3};"
        : "+f"(c[0]), "+f"(c[1]), "+f"(c[2]), "+f"(c[3])
        : "r"(a[0]), "r"(a[1]), "r"(a[2]), "r"(a[3]), "r"(b[0]), "r"(b[1]));
}

extern __shared__ __align__(16) __nv_bfloat16 dsm[];

__global__ __launch_bounds__(256, 2)
void gemm_kernel(const float* __restrict__ bias, float* __restrict__ out) {
    int tid  = threadIdx.x;
    int wid  = tid >> 5, lane = tid & 31;
    int wm   = wid & 1,  wn   = wid >> 1;       // warp grid 2 x 4
    int bm   = blockIdx.x * GBM;
    int bn   = blockIdx.y * GBN;
    int lq   = lane >> 2;
    int lr   = lane & 3;

    int crow = tid >> 1;
    int ckq  = (tid & 1) * 16;

    uint32_t smb = sm32(dsm);

    // ldmatrix per-lane address components
    int arow = (lane & 7) + ((lane >> 3) & 1) * 8;   // A: row within 16
    int akc  = (lane >> 4) * 8;                      // A: k offset 0/8
    int bnof = (lane >> 4) * 8 + (lane & 7);         // B: n within 16
    int bkc  = ((lane >> 3) & 1) * 8;                // B: k offset 0/8

    float acc[4][4][4];
    #pragma unroll
    for (int mi = 0; mi < 4; mi++)
        #pragma unroll
        for (int ni = 0; ni < 4; ni++)
            #pragma unroll
            for (int q = 0; q < 4; q++) acc[mi][ni][q] = 0.f;

    const __nv_bfloat16* gA  = g_Ah + (size_t)(bm + crow) * 512 + ckq;
    const __nv_bfloat16* gAl = g_Al + (size_t)(bm + crow) * 512 + ckq;
    const __nv_bfloat16* gB  = g_Bh + (size_t)(bn + crow) * 512 + ckq;
    const __nv_bfloat16* gBl = g_Bl + (size_t)(bn + crow) * 512 + ckq;

    #define ISSUE_STAGE(c, st) do {                                              \
        int k0 = (c) * GBK;                                                      \
        uint32_t dbase = smb + (uint32_t)((((st)*4)*128 + crow)*AST + ckq) * 2;   \
        cpa16(dbase,                        gA  + k0);                            \
        cpa16(dbase + 16,                   gA  + k0 + 8);                        \
        cpa16(dbase + BUF_ELEMS*2,          gAl + k0);                            \
        cpa16(dbase + BUF_ELEMS*2 + 16,     gAl + k0 + 8);                        \
        cpa16(dbase + 2*BUF_ELEMS*2,        gB  + k0);                            \
        cpa16(dbase + 2*BUF_ELEMS*2 + 16,   gB  + k0 + 8);                        \
        cpa16(dbase + 3*BUF_ELEMS*2,        gBl + k0);                            \
        cpa16(dbase + 3*BUF_ELEMS*2 + 16,   gBl + k0 + 8);                        \
    } while (0)

    ISSUE_STAGE(0, 0);
    asm volatile("cp.async.commit_group;" ::: "memory");
    ISSUE_STAGE(1, 1);
    asm volatile("cp.async.commit_group;" ::: "memory");

    for (int c = 0; c < 16; c++) {
        int st = c & 1;
        asm volatile("cp.async.wait_group 1;" ::: "memory");
        __syncthreads();

        uint32_t sAh = smb + (uint32_t)((st*4 + 0) * BUF_ELEMS) * 2;
        uint32_t sAl = smb + (uint32_t)((st*4 + 1) * BUF_ELEMS) * 2;
        uint32_t sBh = smb + (uint32_t)((st*4 + 2) * BUF_ELEMS) * 2;
        uint32_t sBl = smb + (uint32_t)((st*4 + 3) * BUF_ELEMS) * 2;

        #pragma unroll
        for (int ks = 0; ks < 2; ks++) {
            int kb = ks * 16;
            uint32_t bh[4][2], bl[4][2];
            #pragma unroll
            for (int nip = 0; nip < 2; nip++) {
                int ncol = wn * 32 + nip * 16 + bnof;
                uint32_t off = (uint32_t)(ncol * AST + kb + bkc) * 2;
                uint32_t r[4];
                ldsm4(r, sBh + off);
                bh[nip*2+0][0] = r[0]; bh[nip*2+0][1] = r[1];
                bh[nip*2+1][0] = r[2]; bh[nip*2+1][1] = r[3];
                ldsm4(r, sBl + off);
                bl[nip*2+0][0] = r[0]; bl[nip*2+0][1] = r[1];
                bl[nip*2+1][0] = r[2]; bl[nip*2+1][1] = r[3];
            }
            #pragma unroll
            for (int mi = 0; mi < 4; mi++) {
                int row = wm * 64 + mi * 16 + arow;
                uint32_t off = (uint32_t)(row * AST + kb + akc) * 2;
                uint32_t a[4];
                ldsm4(a, sAh + off);
                #pragma unroll
                for (int ni = 0; ni < 4; ni++) mma16816(acc[mi][ni], a, bh[ni]);
                #pragma unroll
                for (int ni = 0; ni < 4; ni++) mma16816(acc[mi][ni], a, bl[ni]);
                ldsm4(a, sAl + off);
                #pragma unroll
                for (int ni = 0; ni < 4; ni++) mma16816(acc[mi][ni], a, bh[ni]);
            }
        }
        __syncthreads();

        if (c + 2 < 16) ISSUE_STAGE(c + 2, st);
        asm volatile("cp.async.commit_group;" ::: "memory");
    }

    // epilogue: out layout (T, B, C): idx = t*(B*C) + b*C + n, with m = b*512 + t
    #pragma unroll
    for (int mi = 0; mi < 4; mi++) {
        int mrow = bm + wm * 64 + mi * 16 + lq;
        #pragma unroll
        for (int half = 0; half < 2; half++) {
            int m = mrow + half * 8;
            int b = m >> 9;
            int t = m & 511;
            float* op = out + (size_t)t * (BB * CC) + b * CC + bn;
            #pragma unroll
            for (int ni = 0; ni < 4; ni++) {
                int nloc = wn * 32 + ni * 8 + lr * 2;
                float2 v;
                v.x = acc[mi][ni][half * 2 + 0] + bias[bn + nloc];
                v.y = acc[mi][ni][half * 2 + 1] + bias[bn + nloc + 1];
                *(float2*)(op + nloc) = v;
            }
        }
    }
}

// ---------------- launch ------------------------------------------------------------
extern "C" void kernel_launch(void* const* d_in, const int* in_sizes, int n_in,
                              void* d_out, int out_size) {
    const float*         x    = (const float*)d_in[0];
    const unsigned char* mask = (const unsigned char*)d_in[1];
    const int*           tl   = (const int*)d_in[2];
    const float*         W    = (const float*)d_in[3];
    const float*         bias = (const float*)d_in[4];
    float*               out  = (float*)d_out;

    float* asum_out = out + (size_t)TMAX * BB * CC;

    cudaFuncSetAttribute(gemm_kernel, cudaFuncAttributeMaxDynamicSharedMemorySize, SMEM_GEMM);

    sigmoid_kernel<<<(BB * SS) / 256, 256>>>(x, mask);
    scan_kernel<<<BB, 512>>>(tl, asum_out);
    prep_w_kernel<<<(512 * 512 + 255) / 256, 256>>>(W);
    gather_kernel<<<BB * 64 * 2, 128>>>(x);
    gemm_kernel<<<dim3(8192 / GBM, 512 / GBN), 256, SMEM_GEMM>>>(bias, out);
}

// round 8
// speedup vs baseline: 1.9571x; 1.0751x over previous
#include <cuda_runtime.h>
#include <cuda_bf16.h>
#include <math.h>
#include <stdint.h>

// Problem constants
#define SS   4096
#define BB   16
#define CC   512
#define TMAX 512

// ---------------- device scratch (static; no cudaMalloc) ----------------------------
__device__ float g_sig  [BB * SS];          // raw sigmoid
__device__ float g_alpha[BB * SS];          // scaled alpha
__device__ float g_csum [BB * SS];
__device__ int   g_f    [BB * SS];
__device__ __align__(16) __nv_bfloat16 g_Ah[8192 * 512];
__device__ __align__(16) __nv_bfloat16 g_Al[8192 * 512];
__device__ __align__(16) __nv_bfloat16 g_Bh[512 * 512];
__device__ __align__(16) __nv_bfloat16 g_Bl[512 * 512];

__constant__ int c_off[13] = {0,4096,6144,7168,7680,7936,8064,8128,8160,8176,8184,8188,8190};

// ---------------- Phase 1a: fp64 sigmoid spread over the whole chip -----------------
__global__ __launch_bounds__(256)
void sigmoid_kernel(const float* __restrict__ x, const unsigned char* __restrict__ mask) {
    int i = blockIdx.x * 256 + threadIdx.x;    // i = b*SS + s
    int b = i >> 12;
    int s = i & (SS - 1);
    float a = mask[i] ? -10000.0f : x[(size_t)s * (BB*CC) + b * CC + (CC - 1)];
    double sg = 1.0 / (1.0 + exp(-(double)a));
    g_sig[i] = (float)sg;
}

// ---------------- Phase 1b: fp32 reduce + exact JAX-tree cumsum + fire indices ------
__device__ __forceinline__ void downsweep(float* sb, int tid) {
    for (int l = 1; l <= 12; l++) {
        int sz = SS >> l;
        int o  = c_off[l], oi = c_off[l-1];
        for (int i = tid; i < sz; i += 512)
            sb[o + i] = sb[oi + 2*i] + sb[oi + 2*i + 1];
        __syncthreads();
    }
}
__device__ __forceinline__ void upsweep(float* sb, int tid) {
    for (int l = 11; l >= 0; l--) {
        int sz = SS >> l;
        int o  = c_off[l], ou = c_off[l+1];
        for (int i = tid; i < sz; i += 512) {
            float v;
            if (i & 1)          v = sb[ou + (i >> 1)];
            else if (i == 0)    v = sb[o];
            else                v = sb[ou + (i >> 1) - 1] + sb[o + i];
            sb[o + i] = v;
        }
        __syncthreads();
    }
}

__global__ __launch_bounds__(512)
void scan_kernel(const int* __restrict__ tl, float* __restrict__ alpha_sum_out) {
    __shared__ float sb[8192];
    int b   = blockIdx.x;
    int tid = threadIdx.x;

    for (int s = tid; s < SS; s += 512) sb[s] = g_sig[b * SS + s];
    __syncthreads();

    downsweep(sb, tid);
    float asum = sb[c_off[12]];
    if (tid == 0) alpha_sum_out[b] = asum;
    float tlf = (float)tl[b];
    __syncthreads();

    for (int s = tid; s < SS; s += 512) {
        float sc = (sb[s] * tlf) / asum;
        sb[s] = sc;
        g_alpha[b * SS + s] = sc;
    }
    __syncthreads();

    downsweep(sb, tid);
    upsweep(sb, tid);

    for (int s = tid; s < SS; s += 512) {
        float c = sb[s];
        g_csum[b * SS + s] = c;
        g_f  [b * SS + s] = (int)floorf(c + 1e-4f);
    }
}

// ---------------- Phase 1c: W -> bf16 hi/lo, row-major [n][k] -----------------------
__global__ void prep_w_kernel(const float* __restrict__ W) {
    int i = blockIdx.x * 256 + threadIdx.x;
    if (i >= 512 * 512) return;
    int n = i >> 9;
    int k = i & 511;
    float v = (k < 511) ? W[n * 511 + k] : 0.0f;
    __nv_bfloat16 hi = __float2bfloat16(v);
    __nv_bfloat16 lo = __float2bfloat16(v - __bfloat162float(hi));
    g_Bh[i] = hi;
    g_Bl[i] = lo;
}

// ---------------- Phase 2: sparse gather, TT=4, float4 weights, MLP-16 loads --------
#define TT 4

__global__ __launch_bounds__(128)
void gather_kernel(const float* __restrict__ x) {
    int blk   = blockIdx.x;            // b * 256 + tg*2 + chalf
    int b     = blk >> 8;
    int rest  = blk & 255;
    int tg    = rest >> 1;
    int chalf = rest & 1;
    int t0    = tg * TT;
    const int*   f  = g_f     + b * SS;
    const float* al = g_alpha + b * SS;
    const float* cs = g_csum  + b * SS;

    int lo, hi;
    {
        int l = 0, r = SS;
        while (l < r) { int m = (l + r) >> 1; if (f[m] >= t0 - 1) r = m; else l = m + 1; }
        lo = l;
        l = 0; r = SS;
        while (l < r) { int m = (l + r) >> 1; if (f[m] > t0 + TT - 1) r = m; else l = m + 1; }
        hi = (l < SS - 1) ? l : SS - 1;
    }

    __shared__ float4 wbuf[144];       // [row] -> weights for 4 t's; [128..143] zero pad
    int tid = threadIdx.x;
    int c0  = chalf * 256 + tid * 2;   // global channel of .x
    float2 acc[TT];
    #pragma unroll
    for (int tt = 0; tt < TT; tt++) acc[tt] = make_float2(0.f, 0.f);

    if (tid < 16) wbuf[128 + tid] = make_float4(0.f, 0.f, 0.f, 0.f);

    for (int base = lo; base <= hi; base += 128) {
        int s = base + tid;
        float4 wv = make_float4(0.f, 0.f, 0.f, 0.f);
        if (s <= hi) {
            int   d1   = f[s];
            int   d0   = (s == 0) ? 0 : f[s - 1];
            int   fire = d1 - d0;
            float a    = al[s];
            float c    = cs[s];
            float ex   = (fire > 1) ? (float)(fire - 1) : 0.f;
            float rw   = (fire > 0) ? (c - (float)d1) : a;
            float lw   = (a - rw) - ex;
            int   ei   = d0 + 1; if (ei > TMAX - 1) ei = TMAX - 1;
            float exc  = fminf(ex, 1.0f);
            float w[TT];
            #pragma unroll
            for (int tt = 0; tt < TT; tt++) {
                int t = t0 + tt;
                float ww = 0.f;
                if (d1 == t) ww += rw;
                if (d0 == t) ww += lw;
                if (ei == t) ww += exc;
                if (t >= d0 + 2 && t < d1) ww = 1.0f;   // fill overwrite
                w[tt] = ww;
            }
            wv = make_float4(w[0], w[1], w[2], w[3]);
        }
        wbuf[tid] = wv;
        __syncthreads();

        int n = hi - base + 1; if (n > 128) n = 128;
        const float* xp = x + (size_t)base * (BB*CC) + b * CC + c0;

        // software-pipelined: 8 rows in flight + 8 prefetched (clamped; pad weight=0)
        float2 v[8];
        #pragma unroll
        for (int q = 0; q < 8; q++) {
            int r = q < n ? q : n - 1;
            v[q] = *(const float2*)(xp + (size_t)r * (BB*CC));
        }
        for (int j = 0; j < n; j += 8) {
            float2 nv[8];
            #pragma unroll
            for (int q = 0; q < 8; q++) {
                int r = j + 8 + q; r = r < n ? r : n - 1;
                nv[q] = *(const float2*)(xp + (size_t)r * (BB*CC));
            }
            #pragma unroll
            for (int q = 0; q < 8; q++) {
                float4 wq = wbuf[j + q];
                acc[0].x += wq.x * v[q].x; acc[0].y += wq.x * v[q].y;
                acc[1].x += wq.y * v[q].x; acc[1].y += wq.y * v[q].y;
                acc[2].x += wq.z * v[q].x; acc[2].y += wq.z * v[q].y;
                acc[3].x += wq.w * v[q].x; acc[3].y += wq.w * v[q].y;
            }
            #pragma unroll
            for (int q = 0; q < 8; q++) v[q] = nv[q];
        }
        __syncthreads();
    }

    // emit bf16 hi/lo
    #pragma unroll
    for (int tt = 0; tt < TT; tt++) {
        float2 a = acc[tt];
        if (c0 == 510) a.y = 0.f;   // channel 511 excluded
        __nv_bfloat16 h0 = __float2bfloat16(a.x), h1 = __float2bfloat16(a.y);
        __nv_bfloat16 l0 = __float2bfloat16(a.x - __bfloat162float(h0));
        __nv_bfloat16 l1 = __float2bfloat16(a.y - __bfloat162float(h1));
        uint32_t uh = (unsigned)__bfloat16_as_ushort(h0) | ((unsigned)__bfloat16_as_ushort(h1) << 16);
        uint32_t ul = (unsigned)__bfloat16_as_ushort(l0) | ((unsigned)__bfloat16_as_ushort(l1) << 16);
        size_t o = (size_t)(b * 512 + t0 + tt) * 512 + c0;
        *(uint32_t*)&g_Ah[o] = uh;
        *(uint32_t*)&g_Al[o] = ul;
    }
}

// ---------------- Phase 3: bf16 split GEMM, mma.sync + ldmatrix + cp.async ----------
#define GBM 128
#define GBN 128
#define GBK 32
#define AST 40
#define BUF_ELEMS (128 * AST)
#define SMEM_GEMM (2 * 4 * BUF_ELEMS * 2)   // 81920

__device__ __forceinline__ uint32_t sm32(const void* p) {
    uint32_t a;
    asm("{ .reg .u64 t; cvta.to.shared.u64 t, %1; cvt.u32.u64 %0, t; }" : "=r"(a) : "l"(p));
    return a;
}
__device__ __forceinline__ void cpa16(uint32_t dst, const void* src) {
    asm volatile("cp.async.cg.shared.global [%0], [%1], 16;" :: "r"(dst), "l"(src) : "memory");
}
__device__ __forceinline__ void ldsm4(uint32_t* r, uint32_t addr) {
    asm volatile("ldmatrix.sync.aligned.m8n8.x4.shared.b16 {%0,%1,%2,%3}, [%4];"
        : "=r"(r[0]), "=r"(r[1]), "=r"(r[2]), "=r"(r[3]) : "r"(addr));
}
__device__ __forceinline__ void mma16816(float* c, const uint32_t* a, const uint32_t* b) {
    asm volatile("mma.sync.aligned.m16n8k16.row.col.f32.bf16.bf16.f32 "
        "{%0,%1,%2,%3}, {%4,%5,%6,%7}, {%8,%9}, {%0,%1,%2,%3};"
        : "+f"(c[0]), "+f"(c[1]), "+f"(c[2]), "+f"(c[3])
        : "r"(a[0]), "r"(a[1]), "r"(a[2]), "r"(a[3]), "r"(b[0]), "r"(b[1]));
}

extern __shared__ __align__(16) __nv_bfloat16 dsm[];

__global__ __launch_bounds__(256, 2)
void gemm_kernel(const float* __restrict__ bias, const int* __restrict__ tl,
                 float* __restrict__ out) {
    int tid  = threadIdx.x;
    int wid  = tid >> 5, lane = tid & 31;
    int wm   = wid & 1,  wn   = wid >> 1;       // warp grid 2 x 4
    int bm   = blockIdx.x * GBM;
    int bn   = blockIdx.y * GBN;
    int lq   = lane >> 2;
    int lr   = lane & 3;

    // all-zero M-block skip: rows t > tl[b] have zero feats -> out = bias
    {
        int bb  = bm >> 9;          // batch of this block (128 | 512)
        int t0b = bm & 511;         // first t of this block
        if (t0b > tl[bb]) {
            // write bias into all 128 rows x 128 cols of this block
            int rowi = tid >> 1;                 // 0..127
            int cq   = (tid & 1) * 64;           // col offset 0 or 64
            int t    = t0b + rowi;
            float* op = out + (size_t)t * (BB * CC) + bb * CC + bn + cq;
            const float* bp = bias + bn + cq;
            #pragma unroll
            for (int j = 0; j < 64; j += 4)
                *(float4*)(op + j) = *(const float4*)(bp + j);
            return;
        }
    }

    int crow = tid >> 1;
    int ckq  = (tid & 1) * 16;

    uint32_t smb = sm32(dsm);

    // ldmatrix per-lane address components
    int arow = (lane & 7) + ((lane >> 3) & 1) * 8;   // A: row within 16
    int akc  = (lane >> 4) * 8;                      // A: k offset 0/8
    int bnof = (lane >> 4) * 8 + (lane & 7);         // B: n within 16
    int bkc  = ((lane >> 3) & 1) * 8;                // B: k offset 0/8

    float acc[4][4][4];
    #pragma unroll
    for (int mi = 0; mi < 4; mi++)
        #pragma unroll
        for (int ni = 0; ni < 4; ni++)
            #pragma unroll
            for (int q = 0; q < 4; q++) acc[mi][ni][q] = 0.f;

    const __nv_bfloat16* gA  = g_Ah + (size_t)(bm + crow) * 512 + ckq;
    const __nv_bfloat16* gAl = g_Al + (size_t)(bm + crow) * 512 + ckq;
    const __nv_bfloat16* gB  = g_Bh + (size_t)(bn + crow) * 512 + ckq;
    const __nv_bfloat16* gBl = g_Bl + (size_t)(bn + crow) * 512 + ckq;

    #define ISSUE_STAGE(c, st) do {                                              \
        int k0 = (c) * GBK;                                                      \
        uint32_t dbase = smb + (uint32_t)((((st)*4)*128 + crow)*AST + ckq) * 2;   \
        cpa16(dbase,                        gA  + k0);                            \
        cpa16(dbase + 16,                   gA  + k0 + 8);                        \
        cpa16(dbase + BUF_ELEMS*2,          gAl + k0);                            \
        cpa16(dbase + BUF_ELEMS*2 + 16,     gAl + k0 + 8);                        \
        cpa16(dbase + 2*BUF_ELEMS*2,        gB  + k0);                            \
        cpa16(dbase + 2*BUF_ELEMS*2 + 16,   gB  + k0 + 8);                        \
        cpa16(dbase + 3*BUF_ELEMS*2,        gBl + k0);                            \
        cpa16(dbase + 3*BUF_ELEMS*2 + 16,   gBl + k0 + 8);                        \
    } while (0)

    ISSUE_STAGE(0, 0);
    asm volatile("cp.async.commit_group;" ::: "memory");
    ISSUE_STAGE(1, 1);
    asm volatile("cp.async.commit_group;" ::: "memory");

    for (int c = 0; c < 16; c++) {
        int st = c & 1;
        asm volatile("cp.async.wait_group 1;" ::: "memory");
        __syncthreads();

        uint32_t sAh = smb + (uint32_t)((st*4 + 0) * BUF_ELEMS) * 2;
        uint32_t sAl = smb + (uint32_t)((st*4 + 1) * BUF_ELEMS) * 2;
        uint32_t sBh = smb + (uint32_t)((st*4 + 2) * BUF_ELEMS) * 2;
        uint32_t sBl = smb + (uint32_t)((st*4 + 3) * BUF_ELEMS) * 2;

        #pragma unroll
        for (int ks = 0; ks < 2; ks++) {
            int kb = ks * 16;
            uint32_t bh[4][2], bl[4][2];
            #pragma unroll
            for (int nip = 0; nip < 2; nip++) {
                int ncol = wn * 32 + nip * 16 + bnof;
                uint32_t off = (uint32_t)(ncol * AST + kb + bkc) * 2;
                uint32_t r[4];
                ldsm4(r, sBh + off);
                bh[nip*2+0][0] = r[0]; bh[nip*2+0][1] = r[1];
                bh[nip*2+1][0] = r[2]; bh[nip*2+1][1] = r[3];
                ldsm4(r, sBl + off);
                bl[nip*2+0][0] = r[0]; bl[nip*2+0][1] = r[1];
                bl[nip*2+1][0] = r[2]; bl[nip*2+1][1] = r[3];
            }
            #pragma unroll
            for (int mi = 0; mi < 4; mi++) {
                int row = wm * 64 + mi * 16 + arow;
                uint32_t off = (uint32_t)(row * AST + kb + akc) * 2;
                uint32_t a[4];
                ldsm4(a, sAh + off);
                #pragma unroll
                for (int ni = 0; ni < 4; ni++) mma16816(acc[mi][ni], a, bh[ni]);
                #pragma unroll
                for (int ni = 0; ni < 4; ni++) mma16816(acc[mi][ni], a, bl[ni]);
                ldsm4(a, sAl + off);
                #pragma unroll
                for (int ni = 0; ni < 4; ni++) mma16816(acc[mi][ni], a, bh[ni]);
            }
        }
        __syncthreads();

        if (c + 2 < 16) ISSUE_STAGE(c + 2, st);
        asm volatile("cp.async.commit_group;" ::: "memory");
    }

    // epilogue: out layout (T, B, C): idx = t*(B*C) + b*C + n, with m = b*512 + t
    #pragma unroll
    for (int mi = 0; mi < 4; mi++) {
        int mrow = bm + wm * 64 + mi * 16 + lq;
        #pragma unroll
        for (int half = 0; half < 2; half++) {
            int m = mrow + half * 8;
            int b = m >> 9;
            int t = m & 511;
            float* op = out + (size_t)t * (BB * CC) + b * CC + bn;
            #pragma unroll
            for (int ni = 0; ni < 4; ni++) {
                int nloc = wn * 32 + ni * 8 + lr * 2;
                float2 v;
                v.x = acc[mi][ni][half * 2 + 0] + bias[bn + nloc];
                v.y = acc[mi][ni][half * 2 + 1] + bias[bn + nloc + 1];
                *(float2*)(op + nloc) = v;
            }
        }
    }
}

// ---------------- launch ------------------------------------------------------------
extern "C" void kernel_launch(void* const* d_in, const int* in_sizes, int n_in,
                              void* d_out, int out_size) {
    const float*         x    = (const float*)d_in[0];
    const unsigned char* mask = (const unsigned char*)d_in[1];
    const int*           tl   = (const int*)d_in[2];
    const float*         W    = (const float*)d_in[3];
    const float*         bias = (const float*)d_in[4];
    float*               out  = (float*)d_out;

    float* asum_out = out + (size_t)TMAX * BB * CC;

    cudaFuncSetAttribute(gemm_kernel, cudaFuncAttributeMaxDynamicSharedMemorySize, SMEM_GEMM);

    sigmoid_kernel<<<(BB * SS) / 256, 256>>>(x, mask);
    scan_kernel<<<BB, 512>>>(tl, asum_out);
    prep_w_kernel<<<(512 * 512 + 255) / 256, 256>>>(W);
    gather_kernel<<<BB * 128 * 2, 128>>>(x);
    gemm_kernel<<<dim3(8192 / GBM, 512 / GBN), 256, SMEM_GEMM>>>(bias, tl, out);
}

// round 9
// speedup vs baseline: 1.9625x; 1.0027x over previous
#include <cuda_runtime.h>
#include <cuda_bf16.h>
#include <math.h>
#include <stdint.h>

// Problem constants
#define SS   4096
#define BB   16
#define CC   512
#define TMAX 512

// ---------------- device scratch (static; no cudaMalloc) ----------------------------
__device__ float g_sig  [BB * SS];          // raw sigmoid
__device__ float g_alpha[BB * SS];          // scaled alpha
__device__ float g_csum [BB * SS];
__device__ int   g_f    [BB * SS];
__device__ __align__(16) __nv_bfloat16 g_Ah[8192 * 512];
__device__ __align__(16) __nv_bfloat16 g_Al[8192 * 512];
__device__ __align__(16) __nv_bfloat16 g_Bh[512 * 512];
__device__ __align__(16) __nv_bfloat16 g_Bl[512 * 512];

__constant__ int c_off[13] = {0,4096,6144,7168,7680,7936,8064,8128,8160,8176,8184,8188,8190};

// ---------------- Phase 1a: fp64 sigmoid spread over the whole chip -----------------
__global__ __launch_bounds__(256)
void sigmoid_kernel(const float* __restrict__ x, const unsigned char* __restrict__ mask) {
    int i = blockIdx.x * 256 + threadIdx.x;    // i = b*SS + s
    int b = i >> 12;
    int s = i & (SS - 1);
    float a = mask[i] ? -10000.0f : x[(size_t)s * (BB*CC) + b * CC + (CC - 1)];
    double sg = 1.0 / (1.0 + exp(-(double)a));
    g_sig[i] = (float)sg;
}

// ---------------- Phase 1b: fp32 reduce + exact JAX-tree cumsum + fire indices ------
__device__ __forceinline__ void downsweep(float* sb, int tid) {
    for (int l = 1; l <= 12; l++) {
        int sz = SS >> l;
        int o  = c_off[l], oi = c_off[l-1];
        for (int i = tid; i < sz; i += 512)
            sb[o + i] = sb[oi + 2*i] + sb[oi + 2*i + 1];
        __syncthreads();
    }
}
__device__ __forceinline__ void upsweep(float* sb, int tid) {
    for (int l = 11; l >= 0; l--) {
        int sz = SS >> l;
        int o  = c_off[l], ou = c_off[l+1];
        for (int i = tid; i < sz; i += 512) {
            float v;
            if (i & 1)          v = sb[ou + (i >> 1)];
            else if (i == 0)    v = sb[o];
            else                v = sb[ou + (i >> 1) - 1] + sb[o + i];
            sb[o + i] = v;
        }
        __syncthreads();
    }
}

__global__ __launch_bounds__(512)
void scan_kernel(const int* __restrict__ tl, float* __restrict__ alpha_sum_out) {
    __shared__ float sb[8192];
    int b   = blockIdx.x;
    int tid = threadIdx.x;

    for (int s = tid; s < SS; s += 512) sb[s] = g_sig[b * SS + s];
    __syncthreads();

    downsweep(sb, tid);
    float asum = sb[c_off[12]];
    if (tid == 0) alpha_sum_out[b] = asum;
    float tlf = (float)tl[b];
    __syncthreads();

    for (int s = tid; s < SS; s += 512) {
        float sc = (sb[s] * tlf) / asum;
        sb[s] = sc;
        g_alpha[b * SS + s] = sc;
    }
    __syncthreads();

    downsweep(sb, tid);
    upsweep(sb, tid);

    for (int s = tid; s < SS; s += 512) {
        float c = sb[s];
        g_csum[b * SS + s] = c;
        g_f  [b * SS + s] = (int)floorf(c + 1e-4f);
    }
}

// ---------------- Phase 1c: W -> bf16 hi/lo, row-major [n][k] -----------------------
__global__ void prep_w_kernel(const float* __restrict__ W) {
    int i = blockIdx.x * 256 + threadIdx.x;
    if (i >= 512 * 512) return;
    int n = i >> 9;
    int k = i & 511;
    float v = (k < 511) ? W[n * 511 + k] : 0.0f;
    __nv_bfloat16 hi = __float2bfloat16(v);
    __nv_bfloat16 lo = __float2bfloat16(v - __bfloat162float(hi));
    g_Bh[i] = hi;
    g_Bl[i] = lo;
}

// ---------------- Phase 2: sparse gather, TT=4, 256 thr full-row, MLP-8 pipeline ----
#define TT 4

__global__ __launch_bounds__(256)
void gather_kernel(const float* __restrict__ x) {
    int blk = blockIdx.x;              // b * 128 + tg
    int b   = blk >> 7;
    int tg  = blk & 127;
    int t0  = tg * TT;
    const int*   f  = g_f     + b * SS;
    const float* al = g_alpha + b * SS;
    const float* cs = g_csum  + b * SS;

    int lo, hi;
    {
        int l = 0, r = SS;
        while (l < r) { int m = (l + r) >> 1; if (f[m] >= t0 - 1) r = m; else l = m + 1; }
        lo = l;
        l = 0; r = SS;
        while (l < r) { int m = (l + r) >> 1; if (f[m] > t0 + TT - 1) r = m; else l = m + 1; }
        hi = (l < SS - 1) ? l : SS - 1;
    }

    __shared__ float4 wbuf[144];       // [row] -> weights for 4 t's; [128..143] zero pad
    int tid = threadIdx.x;
    int c0  = tid * 2;                 // global channel of .x (0..510)
    float2 acc[TT];
    #pragma unroll
    for (int tt = 0; tt < TT; tt++) acc[tt] = make_float2(0.f, 0.f);

    if (tid >= 128 && tid < 144) wbuf[tid] = make_float4(0.f, 0.f, 0.f, 0.f);

    for (int base = lo; base <= hi; base += 128) {
        if (tid < 128) {
            int s = base + tid;
            float4 wv = make_float4(0.f, 0.f, 0.f, 0.f);
            if (s <= hi) {
                int   d1   = f[s];
                int   d0   = (s == 0) ? 0 : f[s - 1];
                int   fire = d1 - d0;
                float a    = al[s];
                float c    = cs[s];
                float ex   = (fire > 1) ? (float)(fire - 1) : 0.f;
                float rw   = (fire > 0) ? (c - (float)d1) : a;
                float lw   = (a - rw) - ex;
                int   ei   = d0 + 1; if (ei > TMAX - 1) ei = TMAX - 1;
                float exc  = fminf(ex, 1.0f);
                float w[TT];
                #pragma unroll
                for (int tt = 0; tt < TT; tt++) {
                    int t = t0 + tt;
                    float ww = 0.f;
                    if (d1 == t) ww += rw;
                    if (d0 == t) ww += lw;
                    if (ei == t) ww += exc;
                    if (t >= d0 + 2 && t < d1) ww = 1.0f;   // fill overwrite
                    w[tt] = ww;
                }
                wv = make_float4(w[0], w[1], w[2], w[3]);
            }
            wbuf[tid] = wv;
        }
        __syncthreads();

        int n = hi - base + 1; if (n > 128) n = 128;
        const float* xp = x + (size_t)base * (BB*CC) + b * CC + c0;

        // software-pipelined: 8 rows in flight + 8 prefetched (clamped; pad weight=0)
        float2 v[8];
        #pragma unroll
        for (int q = 0; q < 8; q++) {
            int r = q < n ? q : n - 1;
            v[q] = *(const float2*)(xp + (size_t)r * (BB*CC));
        }
        for (int j = 0; j < n; j += 8) {
            float2 nv[8];
            #pragma unroll
            for (int q = 0; q < 8; q++) {
                int r = j + 8 + q; r = r < n ? r : n - 1;
                nv[q] = *(const float2*)(xp + (size_t)r * (BB*CC));
            }
            #pragma unroll
            for (int q = 0; q < 8; q++) {
                float4 wq = wbuf[j + q];
                acc[0].x += wq.x * v[q].x; acc[0].y += wq.x * v[q].y;
                acc[1].x += wq.y * v[q].x; acc[1].y += wq.y * v[q].y;
                acc[2].x += wq.z * v[q].x; acc[2].y += wq.z * v[q].y;
                acc[3].x += wq.w * v[q].x; acc[3].y += wq.w * v[q].y;
            }
            #pragma unroll
            for (int q = 0; q < 8; q++) v[q] = nv[q];
        }
        __syncthreads();
    }

    // emit bf16 hi/lo
    #pragma unroll
    for (int tt = 0; tt < TT; tt++) {
        float2 a = acc[tt];
        if (c0 == 510) a.y = 0.f;   // channel 511 excluded
        __nv_bfloat16 h0 = __float2bfloat16(a.x), h1 = __float2bfloat16(a.y);
        __nv_bfloat16 l0 = __float2bfloat16(a.x - __bfloat162float(h0));
        __nv_bfloat16 l1 = __float2bfloat16(a.y - __bfloat162float(h1));
        uint32_t uh = (unsigned)__bfloat16_as_ushort(h0) | ((unsigned)__bfloat16_as_ushort(h1) << 16);
        uint32_t ul = (unsigned)__bfloat16_as_ushort(l0) | ((unsigned)__bfloat16_as_ushort(l1) << 16);
        size_t o = (size_t)(b * 512 + t0 + tt) * 512 + c0;
        *(uint32_t*)&g_Ah[o] = uh;
        *(uint32_t*)&g_Al[o] = ul;
    }
}

// ---------------- Phase 3: bf16 split GEMM, mma.sync + ldmatrix + cp.async ----------
#define GBM 128
#define GBN 128
#define GBK 32
#define AST 40
#define BUF_ELEMS (128 * AST)
#define SMEM_GEMM (2 * 4 * BUF_ELEMS * 2)   // 81920

__device__ __forceinline__ uint32_t sm32(const void* p) {
    uint32_t a;
    asm("{ .reg .u64 t; cvta.to.shared.u64 t, %1; cvt.u32.u64 %0, t; }" : "=r"(a) : "l"(p));
    return a;
}
__device__ __forceinline__ void cpa16(uint32_t dst, const void* src) {
    asm volatile("cp.async.cg.shared.global [%0], [%1], 16;" :: "r"(dst), "l"(src) : "memory");
}
__device__ __forceinline__ void ldsm4(uint32_t* r, uint32_t addr) {
    asm volatile("ldmatrix.sync.aligned.m8n8.x4.shared.b16 {%0,%1,%2,%3}, [%4];"
        : "=r"(r[0]), "=r"(r[1]), "=r"(r[2]), "=r"(r[3]) : "r"(addr));
}
__device__ __forceinline__ void mma16816(float* c, const uint32_t* a, const uint32_t* b) {
    asm volatile("mma.sync.aligned.m16n8k16.row.col.f32.bf16.bf16.f32 "
        "{%0,%1,%2,%3}, {%4,%5,%6,%7}, {%8,%9}, {%0,%1,%2,%3};"
        : "+f"(c[0]), "+f"(c[1]), "+f"(c[2]), "+f"(c[3])
        : "r"(a[0]), "r"(a[1]), "r"(a[2]), "r"(a[3]), "r"(b[0]), "r"(b[1]));
}

extern __shared__ __align__(16) __nv_bfloat16 dsm[];

__global__ __launch_bounds__(256, 2)
void gemm_kernel(const float* __restrict__ bias, const int* __restrict__ tl,
                 float* __restrict__ out) {
    int tid  = threadIdx.x;
    int wid  = tid >> 5, lane = tid & 31;
    int wm   = wid & 1,  wn   = wid >> 1;       // warp grid 2 x 4
    int bm   = blockIdx.x * GBM;
    int bn   = blockIdx.y * GBN;
    int lq   = lane >> 2;
    int lr   = lane & 3;

    // all-zero M-block skip: rows t > tl[b] have zero feats -> out = bias
    {
        int bb  = bm >> 9;          // batch of this block
        int t0b = bm & 511;         // first t of this block
        if (t0b > tl[bb]) {
            int rowi = tid >> 1;                 // 0..127
            int cq   = (tid & 1) * 64;           // col offset 0 or 64
            int t    = t0b + rowi;
            float* op = out + (size_t)t * (BB * CC) + bb * CC + bn + cq;
            const float* bp = bias + bn + cq;
            #pragma unroll
            for (int j = 0; j < 64; j += 4)
                *(float4*)(op + j) = *(const float4*)(bp + j);
            return;
        }
    }

    int crow = tid >> 1;
    int ckq  = (tid & 1) * 16;

    uint32_t smb = sm32(dsm);

    int arow = (lane & 7) + ((lane >> 3) & 1) * 8;   // A: row within 16
    int akc  = (lane >> 4) * 8;                      // A: k offset 0/8
    int bnof = (lane >> 4) * 8 + (lane & 7);         // B: n within 16
    int bkc  = ((lane >> 3) & 1) * 8;                // B: k offset 0/8

    float acc[4][4][4];
    #pragma unroll
    for (int mi = 0; mi < 4; mi++)
        #pragma unroll
        for (int ni = 0; ni < 4; ni++)
            #pragma unroll
            for (int q = 0; q < 4; q++) acc[mi][ni][q] = 0.f;

    const __nv_bfloat16* gA  = g_Ah + (size_t)(bm + crow) * 512 + ckq;
    const __nv_bfloat16* gAl = g_Al + (size_t)(bm + crow) * 512 + ckq;
    const __nv_bfloat16* gB  = g_Bh + (size_t)(bn + crow) * 512 + ckq;
    const __nv_bfloat16* gBl = g_Bl + (size_t)(bn + crow) * 512 + ckq;

    #define ISSUE_STAGE(c, st) do {                                              \
        int k0 = (c) * GBK;                                                      \
        uint32_t dbase = smb + (uint32_t)((((st)*4)*128 + crow)*AST + ckq) * 2;   \
        cpa16(dbase,                        gA  + k0);                            \
        cpa16(dbase + 16,                   gA  + k0 + 8);                        \
        cpa16(dbase + BUF_ELEMS*2,          gAl + k0);                            \
        cpa16(dbase + BUF_ELEMS*2 + 16,     gAl + k0 + 8);                        \
        cpa16(dbase + 2*BUF_ELEMS*2,        gB  + k0);                            \
        cpa16(dbase + 2*BUF_ELEMS*2 + 16,   gB  + k0 + 8);                        \
        cpa16(dbase + 3*BUF_ELEMS*2,        gBl + k0);                            \
        cpa16(dbase + 3*BUF_ELEMS*2 + 16,   gBl + k0 + 8);                        \
    } while (0)

    ISSUE_STAGE(0, 0);
    asm volatile("cp.async.commit_group;" ::: "memory");
    ISSUE_STAGE(1, 1);
    asm volatile("cp.async.commit_group;" ::: "memory");

    for (int c = 0; c < 16; c++) {
        int st = c & 1;
        asm volatile("cp.async.wait_group 1;" ::: "memory");
        __syncthreads();

        uint32_t sAh = smb + (uint32_t)((st*4 + 0) * BUF_ELEMS) * 2;
        uint32_t sAl = smb + (uint32_t)((st*4 + 1) * BUF_ELEMS) * 2;
        uint32_t sBh = smb + (uint32_t)((st*4 + 2) * BUF_ELEMS) * 2;
        uint32_t sBl = smb + (uint32_t)((st*4 + 3) * BUF_ELEMS) * 2;

        #pragma unroll
        for (int ks = 0; ks < 2; ks++) {
            int kb = ks * 16;
            uint32_t bh[4][2], bl[4][2];
            #pragma unroll
            for (int nip = 0; nip < 2; nip++) {
                int ncol = wn * 32 + nip * 16 + bnof;
                uint32_t off = (uint32_t)(ncol * AST + kb + bkc) * 2;
                uint32_t r[4];
                ldsm4(r, sBh + off);
                bh[nip*2+0][0] = r[0]; bh[nip*2+0][1] = r[1];
                bh[nip*2+1][0] = r[2]; bh[nip*2+1][1] = r[3];
                ldsm4(r, sBl + off);
                bl[nip*2+0][0] = r[0]; bl[nip*2+0][1] = r[1];
                bl[nip*2+1][0] = r[2]; bl[nip*2+1][1] = r[3];
            }
            #pragma unroll
            for (int mi = 0; mi < 4; mi++) {
                int row = wm * 64 + mi * 16 + arow;
                uint32_t off = (uint32_t)(row * AST + kb + akc) * 2;
                uint32_t a[4];
                ldsm4(a, sAh + off);
                #pragma unroll
                for (int ni = 0; ni < 4; ni++) mma16816(acc[mi][ni], a, bh[ni]);
                #pragma unroll
                for (int ni = 0; ni < 4; ni++) mma16816(acc[mi][ni], a, bl[ni]);
                ldsm4(a, sAl + off);
                #pragma unroll
                for (int ni = 0; ni < 4; ni++) mma16816(acc[mi][ni], a, bh[ni]);
            }
        }
        __syncthreads();

        if (c + 2 < 16) ISSUE_STAGE(c + 2, st);
        asm volatile("cp.async.commit_group;" ::: "memory");
    }

    // epilogue: out layout (T, B, C): idx = t*(B*C) + b*C + n, with m = b*512 + t
    #pragma unroll
    for (int mi = 0; mi < 4; mi++) {
        int mrow = bm + wm * 64 + mi * 16 + lq;
        #pragma unroll
        for (int half = 0; half < 2; half++) {
            int m = mrow + half * 8;
            int b = m >> 9;
            int t = m & 511;
            float* op = out + (size_t)t * (BB * CC) + b * CC + bn;
            #pragma unroll
            for (int ni = 0; ni < 4; ni++) {
                int nloc = wn * 32 + ni * 8 + lr * 2;
                float2 v;
                v.x = acc[mi][ni][half * 2 + 0] + bias[bn + nloc];
                v.y = acc[mi][ni][half * 2 + 1] + bias[bn + nloc + 1];
                *(float2*)(op + nloc) = v;
            }
        }
    }
}

// ---------------- launch ------------------------------------------------------------
extern "C" void kernel_launch(void* const* d_in, const int* in_sizes, int n_in,
                              void* d_out, int out_size) {
    const float*         x    = (const float*)d_in[0];
    const unsigned char* mask = (const unsigned char*)d_in[1];
    const int*           tl   = (const int*)d_in[2];
    const float*         W    = (const float*)d_in[3];
    const float*         bias = (const float*)d_in[4];
    float*               out  = (float*)d_out;

    float* asum_out = out + (size_t)TMAX * BB * CC;

    cudaFuncSetAttribute(gemm_kernel, cudaFuncAttributeMaxDynamicSharedMemorySize, SMEM_GEMM);

    sigmoid_kernel<<<(BB * SS) / 256, 256>>>(x, mask);
    scan_kernel<<<BB, 512>>>(tl, asum_out);
    prep_w_kernel<<<(512 * 512 + 255) / 256, 256>>>(W);
    gather_kernel<<<BB * 128, 256>>>(x);
    gemm_kernel<<<dim3(8192 / GBM, 512 / GBN), 256, SMEM_GEMM>>>(bias, tl, out);
}